// round 1
// baseline (speedup 1.0000x reference)
#include <cuda_runtime.h>
#include <math.h>

// ---------------------------------------------------------------------------
// Decoder: N=128 images, 64x64. Pipeline:
//   k_transpose : skinColor [33,256,256] -> g_tex [256,256,36] (pixel-major, padded)
//   k_precompute: per-image lighting math -> ES[3][36], G2[3][3], lightColor[3]; writes b output
//   k_main      : per-pixel gather + fused elementwise, writes all image outputs
// Output tuple layout (flat float32): rgb[ N*3*S ], shade[N*S], spec[N*3*S],
//   blood[N*S], mel[N*S], b[N*2], raw[N*3*S]   (S = 4096)
// ---------------------------------------------------------------------------

#define TEXW   256
#define TEXC   33
#define TEXCP  36           // padded channel count (float4-aligned, zeros in 33..35)
#define IMG2   4096         // 64*64
#define MAXN   256
#define PIXBLK 8            // pixel-chunk blocks per image

__device__ float g_tex[TEXW * TEXW * TEXCP];   // ~9.4 MB transposed LUT
__device__ float g_params[MAXN * 128];         // per-image: ES[108] G2[9] lc[3]

__constant__ float c_S0[33] = {94.8f,104.8f,105.9f,96.8f,113.9f,125.6f,125.5f,121.3f,121.3f,113.5f,113.1f,110.8f,106.5f,108.8f,105.3f,104.4f,100.0f,96.0f,95.1f,89.1f,90.5f,90.3f,88.4f,84.0f,85.1f,81.9f,82.6f,84.9f,81.3f,71.9f,74.3f,76.4f,63.3f};
__constant__ float c_S1[33] = {43.4f,46.3f,43.9f,37.1f,36.7f,35.9f,32.6f,27.9f,24.3f,20.1f,16.2f,13.2f,8.6f,6.1f,4.2f,1.9f,0.0f,-1.6f,-3.5f,-3.5f,-5.8f,-7.2f,-8.6f,-9.5f,-10.9f,-10.7f,-12.0f,-14.0f,-13.6f,-12.0f,-13.3f,-12.9f,-10.6f};
__constant__ float c_S2[33] = {-1.1f,-0.5f,-0.7f,-1.2f,-2.6f,-2.9f,-2.8f,-2.6f,-2.6f,-1.8f,-1.5f,-1.3f,-1.2f,-1.0f,-0.5f,-0.3f,0.0f,0.2f,0.5f,2.1f,3.2f,4.1f,4.7f,5.1f,6.7f,7.3f,8.6f,9.8f,10.2f,8.3f,9.6f,8.5f,7.0f};
__constant__ float c_X[9]  = {3.2406f,-1.537f,-0.498f,-0.968f,1.8758f,0.0415f,0.0557f,-0.204f,1.057f};

// --- skinColor transpose: [33,256,256] -> [p][36] pixel-major -----------------
__global__ void k_transpose(const float* __restrict__ sc) {
    int p = blockIdx.x * blockDim.x + threadIdx.x;
    if (p >= TEXW * TEXW) return;
    float v[TEXCP];
#pragma unroll
    for (int k = 0; k < TEXC; k++) v[k] = sc[(size_t)k * (TEXW * TEXW) + p];
    v[33] = 0.f; v[34] = 0.f; v[35] = 0.f;
    float4* dst = reinterpret_cast<float4*>(g_tex + (size_t)p * TEXCP);
#pragma unroll
    for (int q = 0; q < 9; q++)
        dst[q] = make_float4(v[4*q], v[4*q+1], v[4*q+2], v[4*q+3]);
}

// --- per-image parameter precompute (1 thread per image) ----------------------
__global__ void k_precompute(const float* __restrict__ lighting,
                             const float* __restrict__ illA,
                             const float* __restrict__ illF,
                             const float* __restrict__ pcaMeans,
                             const float* __restrict__ pcaComp,
                             const float* __restrict__ tmat,
                             float* __restrict__ outB, int N) {
    int n = blockIdx.x * blockDim.x + threadIdx.x;
    if (n >= N) return;
    const float* lp = lighting + (size_t)n * 17;

    // softmax over first 14 lighting params
    float mx = lp[0];
#pragma unroll
    for (int j = 1; j < 14; j++) mx = fmaxf(mx, lp[j]);
    float w[14], wsum = 0.f;
#pragma unroll
    for (int j = 0; j < 14; j++) { w[j] = expf(lp[j] - mx); wsum += w[j]; }
    float winv = 1.f / wsum;
    float wA = w[0] * winv, wD = w[1] * winv;
    float fw[12];
#pragma unroll
    for (int j = 0; j < 12; j++) fw[j] = w[j + 2] * winv;

    float colorTemp = 1.f / (1.f + expf(-lp[14]));
    float b0 = 6.f / (1.f + expf(-lp[15])) - 3.f;
    float b1 = 6.f / (1.f + expf(-lp[16])) - 3.f;
    outB[2 * n] = b0; outB[2 * n + 1] = b1;

    // illuminance_d
    float t = colorTemp * 21000.f + 4000.f;
    float it = 1.f / t;
    float x = (t <= 7000.f)
        ? ((-4607000000.f * it + 2967800.f) * it + 99.11f) * it + 0.244063f
        : ((-2006400000.f * it + 1901800.f) * it + 247.48f) * it + 0.23704f;
    float y  = -3.f * x * x + 2.87f * x - 0.275f;
    float m  = 0.0241f + 0.2562f * x - 0.7341f * y;
    float m1 = (-1.3515f - 1.7703f * x + 5.9114f * y) / m;
    float m2 = (0.03f - 31.4424f * x + 30.0717f * y) / m;
    float s[33]; float ssum = 0.f;
#pragma unroll
    for (int k = 0; k < 33; k++) { s[k] = c_S0[k] + m1 * c_S1[k] + m2 * c_S2[k]; ssum += s[k]; }
    float sinv = 1.f / ssum;

    // e = wA*illA + wD*sD + fW @ illF.T ; normalize
    float e[33]; float esum = 0.f;
    for (int k = 0; k < 33; k++) {
        float ef = 0.f;
#pragma unroll
        for (int j = 0; j < 12; j++) ef += fw[j] * illF[k * 12 + j];
        float ev = wA * illA[k] + wD * s[k] * sinv + ef;
        e[k] = ev; esum += ev;
    }
    float einv = 1.f / esum;

    // S = relu(b @ pcaComponents.T + means); lightColor; ES = e*S (padded to 36)
    float lc[3] = {0.f, 0.f, 0.f};
    float* P = g_params + (size_t)n * 128;
    for (int c = 0; c < 3; c++) {
        for (int k = 0; k < 33; k++) {
            int i = c * 33 + k;
            float Sv = fmaxf(b0 * pcaComp[2 * i] + b1 * pcaComp[2 * i + 1] + pcaMeans[i], 0.f);
            lc[c] += Sv;
            P[c * 36 + k] = e[k] * einv * Sv;
        }
        P[c * 36 + 33] = 0.f; P[c * 36 + 34] = 0.f; P[c * 36 + 35] = 0.f;
    }

    // T from bilinear sample of tmatrix [9,128,128] at (b/3) grid coords
    float tx = (b0 * (1.f / 3.f) + 1.f) * 0.5f * 127.f;
    float ty = (b1 * (1.f / 3.f) + 1.f) * 0.5f * 127.f;
    float fx0 = floorf(tx), fy0 = floorf(ty);
    float wx = tx - fx0, wy = ty - fy0;
    int x0 = min(max((int)fx0, 0), 127), y0 = min(max((int)fy0, 0), 127);
    int x1 = min(x0 + 1, 127),           y1 = min(y0 + 1, 127);
    float w00 = (1.f - wx) * (1.f - wy), w01 = wx * (1.f - wy);
    float w10 = (1.f - wx) * wy,         w11 = wx * wy;
    float T[9];
#pragma unroll
    for (int ch = 0; ch < 9; ch++) {
        const float* tp = tmat + (size_t)ch * 128 * 128;
        T[ch] = w00 * tp[y0 * 128 + x0] + w01 * tp[y0 * 128 + x1]
              + w10 * tp[y1 * 128 + x0] + w11 * tp[y1 * 128 + x1];
    }
    // G2[o][c] = (sum_j X[o][j]*T[c][j]) / lc[c]   (folds XYZ2RGB, T, 1/lightColor)
    for (int o = 0; o < 3; o++)
        for (int c = 0; c < 3; c++) {
            float g = c_X[o * 3 + 0] * T[c * 3 + 0]
                    + c_X[o * 3 + 1] * T[c * 3 + 1]
                    + c_X[o * 3 + 2] * T[c * 3 + 2];
            P[108 + o * 3 + c] = g / lc[c];
        }
    P[117] = lc[0]; P[118] = lc[1]; P[119] = lc[2];
}

// --- main per-pixel kernel ----------------------------------------------------
__global__ void __launch_bounds__(256) k_main(
    const float* __restrict__ mel, const float* __restrict__ blood,
    const float* __restrict__ shade, const float* __restrict__ spec,
    float* __restrict__ out, int N)
{
    int n = blockIdx.y;
    __shared__ float sp[120];
    if (threadIdx.x < 120) sp[threadIdx.x] = g_params[(size_t)n * 128 + threadIdx.x];
    __syncthreads();

    size_t NS = (size_t)N * IMG2;
    float* o_rgb   = out;
    float* o_shade = out + 3 * NS;
    float* o_spec  = out + 4 * NS;
    float* o_blood = out + 7 * NS;
    float* o_mel   = out + 8 * NS;
    float* o_raw   = out + 9 * NS + 2 * (size_t)N;

    for (int p = blockIdx.x * blockDim.x + threadIdx.x; p < IMG2; p += PIXBLK * 256) {
        size_t idx = (size_t)n * IMG2 + p;
        float mv = mel[idx], bv = blood[idx], sv = shade[idx];
        float sv0 = spec[((size_t)n * 3 + 0) * IMG2 + p];
        float sv1 = spec[((size_t)n * 3 + 1) * IMG2 + p];
        float sv2 = spec[((size_t)n * 3 + 2) * IMG2 + p];

        float ms = 2.f / (1.f + __expf(-mv)) - 1.f;
        float bs = 2.f / (1.f + __expf(-bv)) - 1.f;

        float tx = (ms + 1.f) * 0.5f * 255.f;
        float ty = (bs + 1.f) * 0.5f * 255.f;
        float fx0 = floorf(tx), fy0 = floorf(ty);
        float wx = tx - fx0, wy = ty - fy0;
        int x0 = min(max((int)fx0, 0), 255), y0 = min(max((int)fy0, 0), 255);
        int x1 = min(x0 + 1, 255),           y1 = min(y0 + 1, 255);
        float w00 = (1.f - wx) * (1.f - wy), w01 = wx * (1.f - wy);
        float w10 = (1.f - wx) * wy,         w11 = wx * wy;

        const float4* t00 = (const float4*)(g_tex + (size_t)(y0 * 256 + x0) * TEXCP);
        const float4* t01 = (const float4*)(g_tex + (size_t)(y0 * 256 + x1) * TEXCP);
        const float4* t10 = (const float4*)(g_tex + (size_t)(y1 * 256 + x0) * TEXCP);
        const float4* t11 = (const float4*)(g_tex + (size_t)(y1 * 256 + x1) * TEXCP);

        float d0 = 0.f, d1 = 0.f, d2 = 0.f;
#pragma unroll
        for (int q = 0; q < 9; q++) {
            float4 a = t00[q], b4 = t01[q], c4 = t10[q], d4 = t11[q];
            float r0 = w00 * a.x + w01 * b4.x + w10 * c4.x + w11 * d4.x;
            float r1 = w00 * a.y + w01 * b4.y + w10 * c4.y + w11 * d4.y;
            float r2 = w00 * a.z + w01 * b4.z + w10 * c4.z + w11 * d4.z;
            float r3 = w00 * a.w + w01 * b4.w + w10 * c4.w + w11 * d4.w;
            int k = q * 4;
            d0 += sp[k]      * r0 + sp[k + 1]      * r1 + sp[k + 2]      * r2 + sp[k + 3]      * r3;
            d1 += sp[36 + k] * r0 + sp[36 + k + 1] * r1 + sp[36 + k + 2] * r2 + sp[36 + k + 3] * r3;
            d2 += sp[72 + k] * r0 + sp[72 + k + 1] * r1 + sp[72 + k + 2] * r2 + sp[72 + k + 3] * r3;
        }

        float shadeE = __expf(sv);
        float se0 = __expf(sv0) * sp[117];
        float se1 = __expf(sv1) * sp[118];
        float se2 = __expf(sv2) * sp[119];
        float raw0 = shadeE * d0 + se0;
        float raw1 = shadeE * d1 + se1;
        float raw2 = shadeE * d2 + se2;
        float rr = fmaxf(sp[108] * raw0 + sp[109] * raw1 + sp[110] * raw2, 0.f);
        float rg = fmaxf(sp[111] * raw0 + sp[112] * raw1 + sp[113] * raw2, 0.f);
        float rb = fmaxf(sp[114] * raw0 + sp[115] * raw1 + sp[116] * raw2, 0.f);

        size_t b3 = ((size_t)n * 3) * IMG2 + p;
        o_rgb[b3] = rr; o_rgb[b3 + IMG2] = rg; o_rgb[b3 + 2 * IMG2] = rb;
        o_shade[idx] = shadeE;
        o_spec[b3] = se0; o_spec[b3 + IMG2] = se1; o_spec[b3 + 2 * IMG2] = se2;
        o_blood[idx] = bs;
        o_mel[idx] = ms;
        o_raw[b3] = raw0; o_raw[b3 + IMG2] = raw1; o_raw[b3 + 2 * IMG2] = raw2;
    }
}

// ---------------------------------------------------------------------------
extern "C" void kernel_launch(void* const* d_in, const int* in_sizes, int n_in,
                              void* d_out, int out_size) {
    const float* lighting  = (const float*)d_in[0];
    const float* mel       = (const float*)d_in[1];
    const float* blood     = (const float*)d_in[2];
    const float* shade     = (const float*)d_in[3];
    const float* spec      = (const float*)d_in[4];
    const float* illA      = (const float*)d_in[5];
    const float* illF      = (const float*)d_in[6];
    const float* pcaMeans  = (const float*)d_in[7];
    const float* pcaComp   = (const float*)d_in[8];
    const float* skinColor = (const float*)d_in[9];
    const float* tmatrix   = (const float*)d_in[10];
    float* out = (float*)d_out;

    int N = in_sizes[0] / 17;            // lighting is [N, 17]
    size_t NS = (size_t)N * IMG2;
    float* outB = out + 9 * NS;          // b section: [N,2]

    k_transpose<<<(TEXW * TEXW + 255) / 256, 256>>>(skinColor);
    k_precompute<<<(N + 127) / 128, 128>>>(lighting, illA, illF, pcaMeans,
                                           pcaComp, tmatrix, outB, N);
    k_main<<<dim3(PIXBLK, N), 256>>>(mel, blood, shade, spec, out, N);
}

// round 2
// speedup vs baseline: 1.6297x; 1.6297x over previous
#include <cuda_runtime.h>
#include <math.h>

// ---------------------------------------------------------------------------
// Decoder pipeline:
//   k_transpose : skinColor [33,256,256] -> g_tex32 [65536][32] (one 128B line
//                 per texel) + g_texE [65536] (channel 32 plane)
//   k_precompute: per-image lighting math -> ES[3][36], G2[3][3], lc[3]; writes b
//   k_main      : warp-cooperative gather (8 lanes per pixel, 4 pixels/warp),
//                 fused elementwise, writes all outputs
// Output tuple layout (flat float32): rgb[N*3*S], shade[N*S], spec[N*3*S],
//   blood[N*S], mel[N*S], b[N*2], raw[N*3*S]   (S = 4096)
// ---------------------------------------------------------------------------

#define TEXW   256
#define NPIX   65536
#define IMG2   4096
#define MAXN   256

__device__ float g_tex32[(NPIX + 16) * 32];   // 8 MB, line-aligned rows (+pad rows)
__device__ float g_texE [(NPIX + 16)];        // 256 KB channel-32 plane
__device__ float g_params[MAXN * 128];        // per-image: ES[108] G2[9] lc[3]

__constant__ float c_S0[33] = {94.8f,104.8f,105.9f,96.8f,113.9f,125.6f,125.5f,121.3f,121.3f,113.5f,113.1f,110.8f,106.5f,108.8f,105.3f,104.4f,100.0f,96.0f,95.1f,89.1f,90.5f,90.3f,88.4f,84.0f,85.1f,81.9f,82.6f,84.9f,81.3f,71.9f,74.3f,76.4f,63.3f};
__constant__ float c_S1[33] = {43.4f,46.3f,43.9f,37.1f,36.7f,35.9f,32.6f,27.9f,24.3f,20.1f,16.2f,13.2f,8.6f,6.1f,4.2f,1.9f,0.0f,-1.6f,-3.5f,-3.5f,-5.8f,-7.2f,-8.6f,-9.5f,-10.9f,-10.7f,-12.0f,-14.0f,-13.6f,-12.0f,-13.3f,-12.9f,-10.6f};
__constant__ float c_S2[33] = {-1.1f,-0.5f,-0.7f,-1.2f,-2.6f,-2.9f,-2.8f,-2.6f,-2.6f,-1.8f,-1.5f,-1.3f,-1.2f,-1.0f,-0.5f,-0.3f,0.0f,0.2f,0.5f,2.1f,3.2f,4.1f,4.7f,5.1f,6.7f,7.3f,8.6f,9.8f,10.2f,8.3f,9.6f,8.5f,7.0f};
__constant__ float c_X[9]  = {3.2406f,-1.537f,-0.498f,-0.968f,1.8758f,0.0415f,0.0557f,-0.204f,1.057f};

// --- transpose: thread T -> (q = T>>16 channel-quad, p = T & 65535) ----------
__global__ void k_transpose(const float* __restrict__ sc) {
    unsigned T = blockIdx.x * blockDim.x + threadIdx.x;   // 0 .. 589823
    unsigned q = T >> 16;
    unsigned p = T & 65535u;
    if (q < 8) {
        float4 v;
        v.x = sc[(size_t)(4*q + 0) * NPIX + p];
        v.y = sc[(size_t)(4*q + 1) * NPIX + p];
        v.z = sc[(size_t)(4*q + 2) * NPIX + p];
        v.w = sc[(size_t)(4*q + 3) * NPIX + p];
        reinterpret_cast<float4*>(g_tex32 + (size_t)p * 32)[q] = v;
    } else if (q == 8) {
        g_texE[p] = sc[(size_t)32 * NPIX + p];
    }
}

// --- per-image parameter precompute (1 thread per image) ---------------------
__global__ void k_precompute(const float* __restrict__ lighting,
                             const float* __restrict__ illA,
                             const float* __restrict__ illF,
                             const float* __restrict__ pcaMeans,
                             const float* __restrict__ pcaComp,
                             const float* __restrict__ tmat,
                             float* __restrict__ outB, int N) {
    int n = blockIdx.x * blockDim.x + threadIdx.x;
    if (n >= N) return;
    const float* lp = lighting + (size_t)n * 17;

    float mx = lp[0];
#pragma unroll
    for (int j = 1; j < 14; j++) mx = fmaxf(mx, lp[j]);
    float w[14], wsum = 0.f;
#pragma unroll
    for (int j = 0; j < 14; j++) { w[j] = expf(lp[j] - mx); wsum += w[j]; }
    float winv = 1.f / wsum;
    float wA = w[0] * winv, wD = w[1] * winv;
    float fw[12];
#pragma unroll
    for (int j = 0; j < 12; j++) fw[j] = w[j + 2] * winv;

    float colorTemp = 1.f / (1.f + expf(-lp[14]));
    float b0 = 6.f / (1.f + expf(-lp[15])) - 3.f;
    float b1 = 6.f / (1.f + expf(-lp[16])) - 3.f;
    outB[2 * n] = b0; outB[2 * n + 1] = b1;

    float t = colorTemp * 21000.f + 4000.f;
    float it = 1.f / t;
    float x = (t <= 7000.f)
        ? ((-4607000000.f * it + 2967800.f) * it + 99.11f) * it + 0.244063f
        : ((-2006400000.f * it + 1901800.f) * it + 247.48f) * it + 0.23704f;
    float y  = -3.f * x * x + 2.87f * x - 0.275f;
    float m  = 0.0241f + 0.2562f * x - 0.7341f * y;
    float m1 = (-1.3515f - 1.7703f * x + 5.9114f * y) / m;
    float m2 = (0.03f - 31.4424f * x + 30.0717f * y) / m;
    float s[33]; float ssum = 0.f;
#pragma unroll
    for (int k = 0; k < 33; k++) { s[k] = c_S0[k] + m1 * c_S1[k] + m2 * c_S2[k]; ssum += s[k]; }
    float sinv = 1.f / ssum;

    float e[33]; float esum = 0.f;
    for (int k = 0; k < 33; k++) {
        float ef = 0.f;
#pragma unroll
        for (int j = 0; j < 12; j++) ef += fw[j] * illF[k * 12 + j];
        float ev = wA * illA[k] + wD * s[k] * sinv + ef;
        e[k] = ev; esum += ev;
    }
    float einv = 1.f / esum;

    float lc[3] = {0.f, 0.f, 0.f};
    float* P = g_params + (size_t)n * 128;
    for (int c = 0; c < 3; c++) {
        for (int k = 0; k < 33; k++) {
            int i = c * 33 + k;
            float Sv = fmaxf(b0 * pcaComp[2 * i] + b1 * pcaComp[2 * i + 1] + pcaMeans[i], 0.f);
            lc[c] += Sv;
            P[c * 36 + k] = e[k] * einv * Sv;
        }
        P[c * 36 + 33] = 0.f; P[c * 36 + 34] = 0.f; P[c * 36 + 35] = 0.f;
    }

    float tx = (b0 * (1.f / 3.f) + 1.f) * 0.5f * 127.f;
    float ty = (b1 * (1.f / 3.f) + 1.f) * 0.5f * 127.f;
    float fx0 = floorf(tx), fy0 = floorf(ty);
    float wx = tx - fx0, wy = ty - fy0;
    int x0 = min(max((int)fx0, 0), 127), y0 = min(max((int)fy0, 0), 127);
    int x1 = min(x0 + 1, 127),           y1 = min(y0 + 1, 127);
    float w00 = (1.f - wx) * (1.f - wy), w01 = wx * (1.f - wy);
    float w10 = (1.f - wx) * wy,         w11 = wx * wy;
    float T[9];
#pragma unroll
    for (int ch = 0; ch < 9; ch++) {
        const float* tp = tmat + (size_t)ch * 128 * 128;
        T[ch] = w00 * tp[y0 * 128 + x0] + w01 * tp[y0 * 128 + x1]
              + w10 * tp[y1 * 128 + x0] + w11 * tp[y1 * 128 + x1];
    }
    for (int o = 0; o < 3; o++)
        for (int c = 0; c < 3; c++) {
            float g = c_X[o * 3 + 0] * T[c * 3 + 0]
                    + c_X[o * 3 + 1] * T[c * 3 + 1]
                    + c_X[o * 3 + 2] * T[c * 3 + 2];
            P[108 + o * 3 + c] = g / lc[c];
        }
    P[117] = lc[0]; P[118] = lc[1]; P[119] = lc[2];
}

// --- main kernel: warp-cooperative gather ------------------------------------
// Warp = 4 pixel-slots x 8 lanes. Phase A: each lane owns 1 pixel (scalar math
// + cheap outputs). Phase B: 8 rounds; round r gathers pixels {8s+r} with 8
// lanes each covering one 16B channel-quad of the 128B texel row. Phase C:
// per-lane finish + coalesced stores.
__global__ void __launch_bounds__(256) k_main(
    const float* __restrict__ mel, const float* __restrict__ blood,
    const float* __restrict__ shade, const float* __restrict__ spec,
    float* __restrict__ out, int N)
{
    const int n   = blockIdx.y;
    const int tid = threadIdx.x;
    const int lane = tid & 31;
    const int sub  = lane & 7;

    __shared__ float sp[120];
    if (tid < 120) sp[tid] = g_params[(size_t)n * 128 + tid];
    __syncthreads();

    const size_t NS = (size_t)N * IMG2;
    float* o_rgb   = out;
    float* o_shade = out + 3 * NS;
    float* o_spec  = out + 4 * NS;
    float* o_blood = out + 7 * NS;
    float* o_mel   = out + 8 * NS;
    float* o_raw   = out + 9 * NS + 2 * (size_t)N;

    // ----- Phase A: per-lane pixel setup -----
    const int p   = blockIdx.x * 256 + tid;       // 0..4095
    const size_t idx = (size_t)n * IMG2 + p;
    const float mv = mel[idx], bv = blood[idx], sv = shade[idx];
    const float sv0 = spec[((size_t)n * 3 + 0) * IMG2 + p];
    const float sv1 = spec[((size_t)n * 3 + 1) * IMG2 + p];
    const float sv2 = spec[((size_t)n * 3 + 2) * IMG2 + p];

    const float ms = 2.f / (1.f + __expf(-mv)) - 1.f;
    const float bs = 2.f / (1.f + __expf(-bv)) - 1.f;

    const float tx = (ms + 1.f) * 127.5f;          // x coord (mel)
    const float ty = (bs + 1.f) * 127.5f;          // y coord (blood)
    const float fx0 = floorf(tx), fy0 = floorf(ty);
    float wx = tx - fx0, wy = ty - fy0;
    const int x0 = min(max((int)fx0, 0), 255);
    const int y0 = min(max((int)fy0, 0), 255);
    const int y1 = min(y0 + 1, 255);
    const int off00 = y0 * 256 + x0;               // t01 = off00+1 (w=0 at edge)
    const int off10 = y1 * 256 + x0;

    const float w00 = (1.f - wx) * (1.f - wy), w01 = wx * (1.f - wy);
    const float w10 = (1.f - wx) * wy,         w11 = wx * wy;

    const float shadeE = __expf(sv);
    const float se0 = __expf(sv0) * sp[117];
    const float se1 = __expf(sv1) * sp[118];
    const float se2 = __expf(sv2) * sp[119];

    // channel-32 contribution (tiny hot plane)
    const float er = w00 * g_texE[off00]     + w01 * g_texE[off00 + 1]
                   + w10 * g_texE[off10]     + w11 * g_texE[off10 + 1];
    float d0 = sp[32]  * er;
    float d1 = sp[68]  * er;
    float d2 = sp[104] * er;

    // cheap outputs now (fully coalesced)
    o_mel[idx]   = ms;
    o_blood[idx] = bs;
    o_shade[idx] = shadeE;
    {
        const size_t b3 = ((size_t)n * 3) * IMG2 + p;
        o_spec[b3] = se0; o_spec[b3 + IMG2] = se1; o_spec[b3 + 2 * IMG2] = se2;
    }

    // ----- Phase B: cooperative gather, 8 rounds -----
    // lane's fixed channel-quad ES weights (channels 4*sub .. 4*sub+3)
    const float4 es0 = *reinterpret_cast<const float4*>(&sp[      4 * sub]);
    const float4 es1 = *reinterpret_cast<const float4*>(&sp[36  + 4 * sub]);
    const float4 es2 = *reinterpret_cast<const float4*>(&sp[72  + 4 * sub]);

#pragma unroll
    for (int r = 0; r < 8; r++) {
        const int src = (lane & 24) + r;
        const int   o00 = __shfl_sync(0xffffffffu, off00, src);
        const int   o10 = __shfl_sync(0xffffffffu, off10, src);
        const float swx = __shfl_sync(0xffffffffu, wx, src);
        const float swy = __shfl_sync(0xffffffffu, wy, src);
        const float sw00 = (1.f - swx) * (1.f - swy), sw01 = swx * (1.f - swy);
        const float sw10 = (1.f - swx) * swy,         sw11 = swx * swy;

        const float4* r0 = reinterpret_cast<const float4*>(g_tex32 + (size_t)o00 * 32) + sub;
        const float4* r1 = reinterpret_cast<const float4*>(g_tex32 + (size_t)o10 * 32) + sub;
        const float4 v00 = r0[0], v01 = r0[8];   // t00, t01 (adjacent texel)
        const float4 v10 = r1[0], v11 = r1[8];   // t10, t11

        const float q0 = sw00 * v00.x + sw01 * v01.x + sw10 * v10.x + sw11 * v11.x;
        const float q1 = sw00 * v00.y + sw01 * v01.y + sw10 * v10.y + sw11 * v11.y;
        const float q2 = sw00 * v00.z + sw01 * v01.z + sw10 * v10.z + sw11 * v11.z;
        const float q3 = sw00 * v00.w + sw01 * v01.w + sw10 * v10.w + sw11 * v11.w;

        float t0 = es0.x * q0 + es0.y * q1 + es0.z * q2 + es0.w * q3;
        float t1 = es1.x * q0 + es1.y * q1 + es1.z * q2 + es1.w * q3;
        float t2 = es2.x * q0 + es2.y * q1 + es2.z * q2 + es2.w * q3;

        t0 += __shfl_xor_sync(0xffffffffu, t0, 4);
        t1 += __shfl_xor_sync(0xffffffffu, t1, 4);
        t2 += __shfl_xor_sync(0xffffffffu, t2, 4);
        t0 += __shfl_xor_sync(0xffffffffu, t0, 2);
        t1 += __shfl_xor_sync(0xffffffffu, t1, 2);
        t2 += __shfl_xor_sync(0xffffffffu, t2, 2);
        t0 += __shfl_xor_sync(0xffffffffu, t0, 1);
        t1 += __shfl_xor_sync(0xffffffffu, t1, 1);
        t2 += __shfl_xor_sync(0xffffffffu, t2, 1);

        if (sub == r) { d0 += t0; d1 += t1; d2 += t2; }
    }

    // ----- Phase C: per-lane finish -----
    const float raw0 = shadeE * d0 + se0;
    const float raw1 = shadeE * d1 + se1;
    const float raw2 = shadeE * d2 + se2;
    const float rr = fmaxf(sp[108] * raw0 + sp[109] * raw1 + sp[110] * raw2, 0.f);
    const float rg = fmaxf(sp[111] * raw0 + sp[112] * raw1 + sp[113] * raw2, 0.f);
    const float rb = fmaxf(sp[114] * raw0 + sp[115] * raw1 + sp[116] * raw2, 0.f);

    const size_t b3 = ((size_t)n * 3) * IMG2 + p;
    o_rgb[b3] = rr; o_rgb[b3 + IMG2] = rg; o_rgb[b3 + 2 * IMG2] = rb;
    o_raw[b3] = raw0; o_raw[b3 + IMG2] = raw1; o_raw[b3 + 2 * IMG2] = raw2;
}

// ---------------------------------------------------------------------------
extern "C" void kernel_launch(void* const* d_in, const int* in_sizes, int n_in,
                              void* d_out, int out_size) {
    const float* lighting  = (const float*)d_in[0];
    const float* mel       = (const float*)d_in[1];
    const float* blood     = (const float*)d_in[2];
    const float* shade     = (const float*)d_in[3];
    const float* spec      = (const float*)d_in[4];
    const float* illA      = (const float*)d_in[5];
    const float* illF      = (const float*)d_in[6];
    const float* pcaMeans  = (const float*)d_in[7];
    const float* pcaComp   = (const float*)d_in[8];
    const float* skinColor = (const float*)d_in[9];
    const float* tmatrix   = (const float*)d_in[10];
    float* out = (float*)d_out;

    int N = in_sizes[0] / 17;            // lighting is [N, 17]
    size_t NS = (size_t)N * IMG2;
    float* outB = out + 9 * NS;          // b section: [N,2]

    k_transpose<<<(9 * NPIX) / 256, 256>>>(skinColor);
    k_precompute<<<(N + 127) / 128, 128>>>(lighting, illA, illF, pcaMeans,
                                           pcaComp, tmatrix, outB, N);
    k_main<<<dim3(16, N), 256>>>(mel, blood, shade, spec, out, N);
}

// round 4
// speedup vs baseline: 1.8480x; 1.1340x over previous
#include <cuda_runtime.h>
#include <cuda_fp16.h>
#include <math.h>

// ---------------------------------------------------------------------------
// Decoder pipeline (2 launches):
//   k_prep : blocks 0..255  -> smem-tiled transpose skinColor[33,256,256]
//                              -> g_tex16 [65536][32] fp16 (64B rows)
//                              -> g_texE2 [65536] half2 (ch32, x-pairs)
//            block 256      -> per-image lighting precompute -> g_params, b out
//   k_main : warp-cooperative gather (8 lanes x 4 pixel-slots), paired x-loads,
//            fused elementwise, all outputs
// Output layout (flat f32): rgb[N*3*S], shade[N*S], spec[N*3*S], blood[N*S],
//   mel[N*S], b[N*2], raw[N*3*S]   (S=4096)
// ---------------------------------------------------------------------------

#define NPIX   65536
#define IMG2   4096
#define MAXN   256

__device__ __half  g_tex16[(NPIX + 16) * 32];   // 4 MB, 64B per texel row (+pad)
__device__ __half2 g_texE2[NPIX + 16];          // 256 KB, (E[p], E[p+1])
__device__ float   g_params[MAXN * 128];        // ES[108] G2[9] lc[3]

__constant__ float c_S0[33] = {94.8f,104.8f,105.9f,96.8f,113.9f,125.6f,125.5f,121.3f,121.3f,113.5f,113.1f,110.8f,106.5f,108.8f,105.3f,104.4f,100.0f,96.0f,95.1f,89.1f,90.5f,90.3f,88.4f,84.0f,85.1f,81.9f,82.6f,84.9f,81.3f,71.9f,74.3f,76.4f,63.3f};
__constant__ float c_S1[33] = {43.4f,46.3f,43.9f,37.1f,36.7f,35.9f,32.6f,27.9f,24.3f,20.1f,16.2f,13.2f,8.6f,6.1f,4.2f,1.9f,0.0f,-1.6f,-3.5f,-3.5f,-5.8f,-7.2f,-8.6f,-9.5f,-10.9f,-10.7f,-12.0f,-14.0f,-13.6f,-12.0f,-13.3f,-12.9f,-10.6f};
__constant__ float c_S2[33] = {-1.1f,-0.5f,-0.7f,-1.2f,-2.6f,-2.9f,-2.8f,-2.6f,-2.6f,-1.8f,-1.5f,-1.3f,-1.2f,-1.0f,-0.5f,-0.3f,0.0f,0.2f,0.5f,2.1f,3.2f,4.1f,4.7f,5.1f,6.7f,7.3f,8.6f,9.8f,10.2f,8.3f,9.6f,8.5f,7.0f};
__constant__ float c_X[9]  = {3.2406f,-1.537f,-0.498f,-0.968f,1.8758f,0.0415f,0.0557f,-0.204f,1.057f};

__device__ __forceinline__ void precompute_image(
    int n, const float* lp, const float* illA, const float* illF,
    const float* pcaMeans, const float* pcaComp, const float* tmat,
    float* outB)
{
    float mx = lp[0];
#pragma unroll
    for (int j = 1; j < 14; j++) mx = fmaxf(mx, lp[j]);
    float w[14], wsum = 0.f;
#pragma unroll
    for (int j = 0; j < 14; j++) { w[j] = expf(lp[j] - mx); wsum += w[j]; }
    float winv = 1.f / wsum;
    float wA = w[0] * winv, wD = w[1] * winv;
    float fw[12];
#pragma unroll
    for (int j = 0; j < 12; j++) fw[j] = w[j + 2] * winv;

    float colorTemp = 1.f / (1.f + expf(-lp[14]));
    float b0 = 6.f / (1.f + expf(-lp[15])) - 3.f;
    float b1 = 6.f / (1.f + expf(-lp[16])) - 3.f;
    outB[2 * n] = b0; outB[2 * n + 1] = b1;

    float t = colorTemp * 21000.f + 4000.f;
    float it = 1.f / t;
    float x = (t <= 7000.f)
        ? ((-4607000000.f * it + 2967800.f) * it + 99.11f) * it + 0.244063f
        : ((-2006400000.f * it + 1901800.f) * it + 247.48f) * it + 0.23704f;
    float y  = -3.f * x * x + 2.87f * x - 0.275f;
    float m  = 0.0241f + 0.2562f * x - 0.7341f * y;
    float m1 = (-1.3515f - 1.7703f * x + 5.9114f * y) / m;
    float m2 = (0.03f - 31.4424f * x + 30.0717f * y) / m;
    float s[33]; float ssum = 0.f;
#pragma unroll
    for (int k = 0; k < 33; k++) { s[k] = c_S0[k] + m1 * c_S1[k] + m2 * c_S2[k]; ssum += s[k]; }
    float sinv = 1.f / ssum;

    float e[33]; float esum = 0.f;
    for (int k = 0; k < 33; k++) {
        float ef = 0.f;
#pragma unroll
        for (int j = 0; j < 12; j++) ef += fw[j] * illF[k * 12 + j];
        float ev = wA * illA[k] + wD * s[k] * sinv + ef;
        e[k] = ev; esum += ev;
    }
    float einv = 1.f / esum;

    float lc[3] = {0.f, 0.f, 0.f};
    float* P = g_params + (size_t)n * 128;
    for (int c = 0; c < 3; c++) {
        for (int k = 0; k < 33; k++) {
            int i = c * 33 + k;
            float Sv = fmaxf(b0 * pcaComp[2 * i] + b1 * pcaComp[2 * i + 1] + pcaMeans[i], 0.f);
            lc[c] += Sv;
            P[c * 36 + k] = e[k] * einv * Sv;
        }
        P[c * 36 + 33] = 0.f; P[c * 36 + 34] = 0.f; P[c * 36 + 35] = 0.f;
    }

    float tx = (b0 * (1.f / 3.f) + 1.f) * 0.5f * 127.f;
    float ty = (b1 * (1.f / 3.f) + 1.f) * 0.5f * 127.f;
    float fx0 = floorf(tx), fy0 = floorf(ty);
    float wx = tx - fx0, wy = ty - fy0;
    int x0 = min(max((int)fx0, 0), 127), y0 = min(max((int)fy0, 0), 127);
    int x1 = min(x0 + 1, 127),           y1 = min(y0 + 1, 127);
    float w00 = (1.f - wx) * (1.f - wy), w01 = wx * (1.f - wy);
    float w10 = (1.f - wx) * wy,         w11 = wx * wy;
    float T[9];
#pragma unroll
    for (int ch = 0; ch < 9; ch++) {
        const float* tp = tmat + (size_t)ch * 128 * 128;
        T[ch] = w00 * tp[y0 * 128 + x0] + w01 * tp[y0 * 128 + x1]
              + w10 * tp[y1 * 128 + x0] + w11 * tp[y1 * 128 + x1];
    }
    for (int o = 0; o < 3; o++)
        for (int c = 0; c < 3; c++) {
            float g = c_X[o * 3 + 0] * T[c * 3 + 0]
                    + c_X[o * 3 + 1] * T[c * 3 + 1]
                    + c_X[o * 3 + 2] * T[c * 3 + 2];
            P[108 + o * 3 + c] = g / lc[c];
        }
    P[117] = lc[0]; P[118] = lc[1]; P[119] = lc[2];
}

// --- prep: transpose (blocks 0..255) + precompute (block 256) ----------------
#define TROW 40   // smem row pitch in halves (80B, 16B-multiple)
__global__ void __launch_bounds__(256) k_prep(
    const float* __restrict__ sc,
    const float* __restrict__ lighting, const float* __restrict__ illA,
    const float* __restrict__ illF, const float* __restrict__ pcaMeans,
    const float* __restrict__ pcaComp, const float* __restrict__ tmat,
    float* __restrict__ outB, int N)
{
    const int bid = blockIdx.x;
    const int tid = threadIdx.x;

    if (bid < 256) {
        __shared__ __align__(16) __half tile[256 * TROW];
        __shared__ float  s32[257];
        const int base = bid * 256;
        // coalesced channel reads -> smem (fp16)
#pragma unroll 4
        for (int c = 0; c < 32; c++)
            tile[tid * TROW + c] = __float2half_rn(sc[(size_t)c * NPIX + base + tid]);
        s32[tid] = sc[(size_t)32 * NPIX + base + tid];
        if (tid == 0) s32[256] = sc[(size_t)32 * NPIX + min(base + 256, NPIX - 1)];
        __syncthreads();
        // ch32 pair plane
        g_texE2[base + tid] = __floats2half2_rn(s32[tid], s32[tid + 1]);
        // packed coalesced row writes: 1024 uint4 per block, 4 per thread
        uint4* dst = reinterpret_cast<uint4*>(g_tex16) + (size_t)base * 4;
#pragma unroll
        for (int j = 0; j < 4; j++) {
            int i = tid + 256 * j;           // 0..1023
            int texel = i >> 2, part = i & 3;
            const uint4* srcu = reinterpret_cast<const uint4*>(tile + texel * TROW) + part;
            dst[(size_t)texel * 4 + part] = *srcu;
        }
    } else {
        int n = tid;
        if (n < N)
            precompute_image(n, lighting + (size_t)n * 17, illA, illF,
                             pcaMeans, pcaComp, tmat, outB);
    }
}

// --- main kernel -------------------------------------------------------------
// Warp = 4 pixel-slots x 8 lanes. Lane owns 1 pixel (phase A/C). Phase B:
// 8 rounds; round r gathers pixels {slot*8 + r}: lane sub covers x-side
// (sub>>2) and channel octet (sub&3) via one 16B load per y-row (paired
// x-rows are contiguous 128B). Butterfly-reduce over 8 lanes.
__global__ void __launch_bounds__(256) k_main(
    const float* __restrict__ mel, const float* __restrict__ blood,
    const float* __restrict__ shade, const float* __restrict__ spec,
    float* __restrict__ out, int N)
{
    const int n    = blockIdx.y;
    const int tid  = threadIdx.x;
    const int lane = tid & 31;
    const int sub  = lane & 7;

    __shared__ float sp[120];
    if (tid < 120) sp[tid] = g_params[(size_t)n * 128 + tid];
    __syncthreads();

    const size_t NS = (size_t)N * IMG2;
    float* o_rgb   = out;
    float* o_shade = out + 3 * NS;
    float* o_spec  = out + 4 * NS;
    float* o_blood = out + 7 * NS;
    float* o_mel   = out + 8 * NS;
    float* o_raw   = out + 9 * NS + 2 * (size_t)N;

    // ----- Phase A -----
    const int p   = blockIdx.x * 256 + tid;
    const size_t idx = (size_t)n * IMG2 + p;
    const float mv = mel[idx], bv = blood[idx], sv = shade[idx];
    const float sv0 = spec[((size_t)n * 3 + 0) * IMG2 + p];
    const float sv1 = spec[((size_t)n * 3 + 1) * IMG2 + p];
    const float sv2 = spec[((size_t)n * 3 + 2) * IMG2 + p];

    const float ms = 2.f / (1.f + __expf(-mv)) - 1.f;
    const float bs = 2.f / (1.f + __expf(-bv)) - 1.f;

    const float tx = (ms + 1.f) * 127.5f;
    const float ty = (bs + 1.f) * 127.5f;
    const float fx0 = floorf(tx), fy0 = floorf(ty);
    float wx = tx - fx0, wy = ty - fy0;
    const int x0 = min(max((int)fx0, 0), 255);
    const int y0 = min(max((int)fy0, 0), 255);
    const int y1 = min(y0 + 1, 255);
    const int off00 = y0 * 256 + x0;
    const int off10 = y1 * 256 + x0;

    const float w00 = (1.f - wx) * (1.f - wy), w01 = wx * (1.f - wy);
    const float w10 = (1.f - wx) * wy,         w11 = wx * wy;

    const float shadeE = __expf(sv);
    const float se0 = __expf(sv0) * sp[117];
    const float se1 = __expf(sv1) * sp[118];
    const float se2 = __expf(sv2) * sp[119];

    // channel-32: half2 pair loads (2 per pixel)
    const float2 e0 = __half22float2(g_texE2[off00]);
    const float2 e1 = __half22float2(g_texE2[off10]);
    const float er = w00 * e0.x + w01 * e0.y + w10 * e1.x + w11 * e1.y;
    float d0 = sp[32]  * er;
    float d1 = sp[68]  * er;
    float d2 = sp[104] * er;

    o_mel[idx]   = ms;
    o_blood[idx] = bs;
    o_shade[idx] = shadeE;
    {
        const size_t b3 = ((size_t)n * 3) * IMG2 + p;
        o_spec[b3] = se0; o_spec[b3 + IMG2] = se1; o_spec[b3 + 2 * IMG2] = se2;
    }

    // ----- Phase B -----
    const int chq = (sub & 3) * 2;            // float4 pair index within ES row
    const float4 esA0 = *reinterpret_cast<const float4*>(&sp[      4 * chq]);
    const float4 esA1 = *reinterpret_cast<const float4*>(&sp[      4 * chq + 4]);
    const float4 esB0 = *reinterpret_cast<const float4*>(&sp[36  + 4 * chq]);
    const float4 esB1 = *reinterpret_cast<const float4*>(&sp[36  + 4 * chq + 4]);
    const float4 esC0 = *reinterpret_cast<const float4*>(&sp[72  + 4 * chq]);
    const float4 esC1 = *reinterpret_cast<const float4*>(&sp[72  + 4 * chq + 4]);

    const uint4* texu = reinterpret_cast<const uint4*>(g_tex16);

#pragma unroll
    for (int r = 0; r < 8; r++) {
        const int src = (lane & 24) + r;
        const int   o00 = __shfl_sync(0xffffffffu, off00, src);
        const int   o10 = __shfl_sync(0xffffffffu, off10, src);
        const float swx = __shfl_sync(0xffffffffu, wx, src);
        const float swy = __shfl_sync(0xffffffffu, wy, src);
        const float wxs = (sub < 4) ? (1.f - swx) : swx;
        const float ay  = wxs * (1.f - swy);
        const float by  = wxs * swy;

        const uint4 vy0 = texu[(size_t)o00 * 4 + sub];
        const uint4 vy1 = texu[(size_t)o10 * 4 + sub];

        float t0, t1, t2;
        {
            const __half2* h0 = reinterpret_cast<const __half2*>(&vy0);
            const __half2* h1 = reinterpret_cast<const __half2*>(&vy1);
            float2 a0 = __half22float2(h0[0]), b0 = __half22float2(h1[0]);
            float2 a1 = __half22float2(h0[1]), b1 = __half22float2(h1[1]);
            float2 a2 = __half22float2(h0[2]), b2 = __half22float2(h1[2]);
            float2 a3 = __half22float2(h0[3]), b3 = __half22float2(h1[3]);
            const float r0 = ay * a0.x + by * b0.x;
            const float r1 = ay * a0.y + by * b0.y;
            const float r2 = ay * a1.x + by * b1.x;
            const float r3 = ay * a1.y + by * b1.y;
            const float r4 = ay * a2.x + by * b2.x;
            const float r5 = ay * a2.y + by * b2.y;
            const float r6 = ay * a3.x + by * b3.x;
            const float r7 = ay * a3.y + by * b3.y;
            t0 = esA0.x*r0 + esA0.y*r1 + esA0.z*r2 + esA0.w*r3
               + esA1.x*r4 + esA1.y*r5 + esA1.z*r6 + esA1.w*r7;
            t1 = esB0.x*r0 + esB0.y*r1 + esB0.z*r2 + esB0.w*r3
               + esB1.x*r4 + esB1.y*r5 + esB1.z*r6 + esB1.w*r7;
            t2 = esC0.x*r0 + esC0.y*r1 + esC0.z*r2 + esC0.w*r3
               + esC1.x*r4 + esC1.y*r5 + esC1.z*r6 + esC1.w*r7;
        }

        t0 += __shfl_xor_sync(0xffffffffu, t0, 4);
        t1 += __shfl_xor_sync(0xffffffffu, t1, 4);
        t2 += __shfl_xor_sync(0xffffffffu, t2, 4);
        t0 += __shfl_xor_sync(0xffffffffu, t0, 2);
        t1 += __shfl_xor_sync(0xffffffffu, t1, 2);
        t2 += __shfl_xor_sync(0xffffffffu, t2, 2);
        t0 += __shfl_xor_sync(0xffffffffu, t0, 1);
        t1 += __shfl_xor_sync(0xffffffffu, t1, 1);
        t2 += __shfl_xor_sync(0xffffffffu, t2, 1);

        if (sub == r) { d0 += t0; d1 += t1; d2 += t2; }
    }

    // ----- Phase C -----
    const float raw0 = shadeE * d0 + se0;
    const float raw1 = shadeE * d1 + se1;
    const float raw2 = shadeE * d2 + se2;
    const float rr = fmaxf(sp[108] * raw0 + sp[109] * raw1 + sp[110] * raw2, 0.f);
    const float rg = fmaxf(sp[111] * raw0 + sp[112] * raw1 + sp[113] * raw2, 0.f);
    const float rb = fmaxf(sp[114] * raw0 + sp[115] * raw1 + sp[116] * raw2, 0.f);

    const size_t b3 = ((size_t)n * 3) * IMG2 + p;
    o_rgb[b3] = rr; o_rgb[b3 + IMG2] = rg; o_rgb[b3 + 2 * IMG2] = rb;
    o_raw[b3] = raw0; o_raw[b3 + IMG2] = raw1; o_raw[b3 + 2 * IMG2] = raw2;
}

// ---------------------------------------------------------------------------
extern "C" void kernel_launch(void* const* d_in, const int* in_sizes, int n_in,
                              void* d_out, int out_size) {
    const float* lighting  = (const float*)d_in[0];
    const float* mel       = (const float*)d_in[1];
    const float* blood     = (const float*)d_in[2];
    const float* shade     = (const float*)d_in[3];
    const float* spec      = (const float*)d_in[4];
    const float* illA      = (const float*)d_in[5];
    const float* illF      = (const float*)d_in[6];
    const float* pcaMeans  = (const float*)d_in[7];
    const float* pcaComp   = (const float*)d_in[8];
    const float* skinColor = (const float*)d_in[9];
    const float* tmatrix   = (const float*)d_in[10];
    float* out = (float*)d_out;

    int N = in_sizes[0] / 17;            // lighting [N,17]
    size_t NS = (size_t)N * IMG2;
    float* outB = out + 9 * NS;

    k_prep<<<257, 256>>>(skinColor, lighting, illA, illF, pcaMeans,
                         pcaComp, tmatrix, outB, N);
    k_main<<<dim3(16, N), 256>>>(mel, blood, shade, spec, out, N);
}

// round 5
// speedup vs baseline: 2.0136x; 1.0896x over previous
#include <cuda_runtime.h>
#include <cuda_fp16.h>
#include <math.h>

// ---------------------------------------------------------------------------
// Decoder pipeline (2 launches):
//   k_prep : blocks 0..255 -> transpose skinColor[33,256,256] ->
//              g_tex16 [65536][32] fp16 (64B rows), g_texE4 quad plane (8B/texel)
//            block 256     -> per-image lighting precompute -> g_params, b out
//   k_main : warp-cooperative gather (8 lanes x 4 pixel-slots), paired x-loads,
//            half2 bilinear+dot, fused elementwise, all outputs
// Output layout (flat f32): rgb[N*3*S], shade[N*S], spec[N*3*S], blood[N*S],
//   mel[N*S], b[N*2], raw[N*3*S]   (S=4096)
// ---------------------------------------------------------------------------

#define NPIX   65536
#define IMG2   4096
#define MAXN   256

__device__ __half  g_tex16[(NPIX + 16) * 32];   // 4 MB, 64B per texel row (+pad)
__device__ uint2   g_texE4[NPIX + 16];          // 512 KB: (E[y][x],E[y][x+1] | E[y+1][x],E[y+1][x+1])
__device__ float   g_params[MAXN * 128];        // ES[108] G2[9] lc[3]

__constant__ float c_S0[33] = {94.8f,104.8f,105.9f,96.8f,113.9f,125.6f,125.5f,121.3f,121.3f,113.5f,113.1f,110.8f,106.5f,108.8f,105.3f,104.4f,100.0f,96.0f,95.1f,89.1f,90.5f,90.3f,88.4f,84.0f,85.1f,81.9f,82.6f,84.9f,81.3f,71.9f,74.3f,76.4f,63.3f};
__constant__ float c_S1[33] = {43.4f,46.3f,43.9f,37.1f,36.7f,35.9f,32.6f,27.9f,24.3f,20.1f,16.2f,13.2f,8.6f,6.1f,4.2f,1.9f,0.0f,-1.6f,-3.5f,-3.5f,-5.8f,-7.2f,-8.6f,-9.5f,-10.9f,-10.7f,-12.0f,-14.0f,-13.6f,-12.0f,-13.3f,-12.9f,-10.6f};
__constant__ float c_S2[33] = {-1.1f,-0.5f,-0.7f,-1.2f,-2.6f,-2.9f,-2.8f,-2.6f,-2.6f,-1.8f,-1.5f,-1.3f,-1.2f,-1.0f,-0.5f,-0.3f,0.0f,0.2f,0.5f,2.1f,3.2f,4.1f,4.7f,5.1f,6.7f,7.3f,8.6f,9.8f,10.2f,8.3f,9.6f,8.5f,7.0f};
__constant__ float c_X[9]  = {3.2406f,-1.537f,-0.498f,-0.968f,1.8758f,0.0415f,0.0557f,-0.204f,1.057f};

__device__ __forceinline__ void precompute_image(
    int n, const float* lp, const float* illA, const float* illF,
    const float* pcaMeans, const float* pcaComp, const float* tmat,
    float* outB)
{
    float mx = lp[0];
#pragma unroll
    for (int j = 1; j < 14; j++) mx = fmaxf(mx, lp[j]);
    float w[14], wsum = 0.f;
#pragma unroll
    for (int j = 0; j < 14; j++) { w[j] = expf(lp[j] - mx); wsum += w[j]; }
    float winv = 1.f / wsum;
    float wA = w[0] * winv, wD = w[1] * winv;
    float fw[12];
#pragma unroll
    for (int j = 0; j < 12; j++) fw[j] = w[j + 2] * winv;

    float colorTemp = 1.f / (1.f + expf(-lp[14]));
    float b0 = 6.f / (1.f + expf(-lp[15])) - 3.f;
    float b1 = 6.f / (1.f + expf(-lp[16])) - 3.f;
    outB[2 * n] = b0; outB[2 * n + 1] = b1;

    float t = colorTemp * 21000.f + 4000.f;
    float it = 1.f / t;
    float x = (t <= 7000.f)
        ? ((-4607000000.f * it + 2967800.f) * it + 99.11f) * it + 0.244063f
        : ((-2006400000.f * it + 1901800.f) * it + 247.48f) * it + 0.23704f;
    float y  = -3.f * x * x + 2.87f * x - 0.275f;
    float m  = 0.0241f + 0.2562f * x - 0.7341f * y;
    float m1 = (-1.3515f - 1.7703f * x + 5.9114f * y) / m;
    float m2 = (0.03f - 31.4424f * x + 30.0717f * y) / m;
    float s[33]; float ssum = 0.f;
#pragma unroll
    for (int k = 0; k < 33; k++) { s[k] = c_S0[k] + m1 * c_S1[k] + m2 * c_S2[k]; ssum += s[k]; }
    float sinv = 1.f / ssum;

    float e[33]; float esum = 0.f;
    for (int k = 0; k < 33; k++) {
        float ef = 0.f;
#pragma unroll
        for (int j = 0; j < 12; j++) ef += fw[j] * illF[k * 12 + j];
        float ev = wA * illA[k] + wD * s[k] * sinv + ef;
        e[k] = ev; esum += ev;
    }
    float einv = 1.f / esum;

    float lc[3] = {0.f, 0.f, 0.f};
    float* P = g_params + (size_t)n * 128;
    for (int c = 0; c < 3; c++) {
        for (int k = 0; k < 33; k++) {
            int i = c * 33 + k;
            float Sv = fmaxf(b0 * pcaComp[2 * i] + b1 * pcaComp[2 * i + 1] + pcaMeans[i], 0.f);
            lc[c] += Sv;
            P[c * 36 + k] = e[k] * einv * Sv;
        }
        P[c * 36 + 33] = 0.f; P[c * 36 + 34] = 0.f; P[c * 36 + 35] = 0.f;
    }

    float tx = (b0 * (1.f / 3.f) + 1.f) * 0.5f * 127.f;
    float ty = (b1 * (1.f / 3.f) + 1.f) * 0.5f * 127.f;
    float fx0 = floorf(tx), fy0 = floorf(ty);
    float wx = tx - fx0, wy = ty - fy0;
    int x0 = min(max((int)fx0, 0), 127), y0 = min(max((int)fy0, 0), 127);
    int x1 = min(x0 + 1, 127),           y1 = min(y0 + 1, 127);
    float w00 = (1.f - wx) * (1.f - wy), w01 = wx * (1.f - wy);
    float w10 = (1.f - wx) * wy,         w11 = wx * wy;
    float T[9];
#pragma unroll
    for (int ch = 0; ch < 9; ch++) {
        const float* tp = tmat + (size_t)ch * 128 * 128;
        T[ch] = w00 * tp[y0 * 128 + x0] + w01 * tp[y0 * 128 + x1]
              + w10 * tp[y1 * 128 + x0] + w11 * tp[y1 * 128 + x1];
    }
    for (int o = 0; o < 3; o++)
        for (int c = 0; c < 3; c++) {
            float g = c_X[o * 3 + 0] * T[c * 3 + 0]
                    + c_X[o * 3 + 1] * T[c * 3 + 1]
                    + c_X[o * 3 + 2] * T[c * 3 + 2];
            P[108 + o * 3 + c] = g / lc[c];
        }
    P[117] = lc[0]; P[118] = lc[1]; P[119] = lc[2];
}

// --- prep: transpose (blocks 0..255) + precompute (block 256) ----------------
#define TROW 40   // smem row pitch in halves (80B, 16B-multiple)
__global__ void __launch_bounds__(256) k_prep(
    const float* __restrict__ sc,
    const float* __restrict__ lighting, const float* __restrict__ illA,
    const float* __restrict__ illF, const float* __restrict__ pcaMeans,
    const float* __restrict__ pcaComp, const float* __restrict__ tmat,
    float* __restrict__ outB, int N)
{
    const int bid = blockIdx.x;
    const int tid = threadIdx.x;

    if (bid < 256) {
        __shared__ __align__(16) __half tile[256 * TROW];
        const int base = bid * 256;
        const int p = base + tid;

        // E-plane quad (clamped indices; clamped entries are never weighted)
        const float* sc32 = sc + (size_t)32 * NPIX;
        const int pn  = min(p + 1,   NPIX - 1);
        const int pd  = min(p + 256, NPIX - 1);
        const int pdn = min(p + 257, NPIX - 1);
        float ea = sc32[p], eb = sc32[pn], ec = sc32[pd], ed = sc32[pdn];

        // fully-unrolled channel loads (MLP=32), then smem writes
        float v[32];
#pragma unroll
        for (int c = 0; c < 32; c++) v[c] = sc[(size_t)c * NPIX + p];
#pragma unroll
        for (int c = 0; c < 32; c++) tile[tid * TROW + c] = __float2half_rn(v[c]);

        {
            __half2 top = __floats2half2_rn(ea, eb);
            __half2 bot = __floats2half2_rn(ec, ed);
            uint2 u;
            u.x = *reinterpret_cast<unsigned*>(&top);
            u.y = *reinterpret_cast<unsigned*>(&bot);
            g_texE4[p] = u;
        }
        __syncthreads();

        // packed coalesced row writes: 1024 uint4 per block, 4 per thread
        uint4* dst = reinterpret_cast<uint4*>(g_tex16) + (size_t)base * 4;
#pragma unroll
        for (int j = 0; j < 4; j++) {
            int i = tid + 256 * j;           // 0..1023
            int texel = i >> 2, part = i & 3;
            const uint4* srcu = reinterpret_cast<const uint4*>(tile + texel * TROW) + part;
            dst[(size_t)texel * 4 + part] = *srcu;
        }
    } else {
        int n = tid;
        if (n < N)
            precompute_image(n, lighting + (size_t)n * 17, illA, illF,
                             pcaMeans, pcaComp, tmat, outB);
    }
}

// --- main kernel -------------------------------------------------------------
// Warp = 4 pixel-slots x 8 lanes. Lane owns 1 pixel (phase A/C). Phase B:
// 8 rounds; round r gathers pixel {slot*8+r}: lane sub covers x-side (sub>>2)
// and channel octet (sub&3) via one 16B load per y-row (x-pair rows contiguous
// 128B). Bilinear + ES dots in half2; butterfly-reduce in fp32.
__global__ void __launch_bounds__(256, 4) k_main(
    const float* __restrict__ mel, const float* __restrict__ blood,
    const float* __restrict__ shade, const float* __restrict__ spec,
    float* __restrict__ out, int N)
{
    const int n    = blockIdx.y;
    const int tid  = threadIdx.x;
    const int lane = tid & 31;
    const int sub  = lane & 7;

    __shared__ float sp[120];
    if (tid < 120) sp[tid] = g_params[(size_t)n * 128 + tid];
    __syncthreads();

    const size_t NS = (size_t)N * IMG2;
    float* o_rgb   = out;
    float* o_shade = out + 3 * NS;
    float* o_spec  = out + 4 * NS;
    float* o_blood = out + 7 * NS;
    float* o_mel   = out + 8 * NS;
    float* o_raw   = out + 9 * NS + 2 * (size_t)N;

    // ----- Phase A -----
    const int p   = blockIdx.x * 256 + tid;
    const size_t idx = (size_t)n * IMG2 + p;
    const float mv = mel[idx], bv = blood[idx], sv = shade[idx];
    const float sv0 = spec[((size_t)n * 3 + 0) * IMG2 + p];
    const float sv1 = spec[((size_t)n * 3 + 1) * IMG2 + p];
    const float sv2 = spec[((size_t)n * 3 + 2) * IMG2 + p];

    const float ms = 2.f / (1.f + __expf(-mv)) - 1.f;
    const float bs = 2.f / (1.f + __expf(-bv)) - 1.f;

    const float tx = (ms + 1.f) * 127.5f;
    const float ty = (bs + 1.f) * 127.5f;
    const float fx0 = floorf(tx), fy0 = floorf(ty);
    float wx = tx - fx0, wy = ty - fy0;
    const int x0 = min(max((int)fx0, 0), 255);
    const int y0 = min(max((int)fy0, 0), 255);
    const int y1 = min(y0 + 1, 255);
    const int off00 = y0 * 256 + x0;     // < 65536
    const int off10 = y1 * 256 + x0;     // < 65536

    const float w00 = (1.f - wx) * (1.f - wy), w01 = wx * (1.f - wy);
    const float w10 = (1.f - wx) * wy,         w11 = wx * wy;

    const float shadeE = __expf(sv);
    const float se0 = __expf(sv0) * sp[117];
    const float se1 = __expf(sv1) * sp[118];
    const float se2 = __expf(sv2) * sp[119];

    // channel-32: one 8B quad load per pixel
    float er;
    {
        uint2 u = g_texE4[off00];
        __half2 th = *reinterpret_cast<__half2*>(&u.x);
        __half2 bh = *reinterpret_cast<__half2*>(&u.y);
        float2 tf = __half22float2(th);
        float2 bf = __half22float2(bh);
        er = w00 * tf.x + w01 * tf.y + w10 * bf.x + w11 * bf.y;
    }
    float d0 = sp[32]  * er;
    float d1 = sp[68]  * er;
    float d2 = sp[104] * er;

    o_mel[idx]   = ms;
    o_blood[idx] = bs;
    o_shade[idx] = shadeE;
    {
        const size_t b3 = ((size_t)n * 3) * IMG2 + p;
        o_spec[b3] = se0; o_spec[b3 + IMG2] = se1; o_spec[b3 + 2 * IMG2] = se2;
    }

    // packed per-pixel gather state for shuffles
    const unsigned packedOff = (unsigned)off00 | ((unsigned)off10 << 16);
    unsigned wbits;
    {
        __half2 wpack = __floats2half2_rn(wx, wy);
        wbits = *reinterpret_cast<unsigned*>(&wpack);
    }

    // ----- Phase B -----
    // lane's channel octet: channels k0 = (sub&3)*8 .. k0+7, as half2 ES weights
    const int k0 = (sub & 3) * 8;
    __half2 esA[4], esB[4], esC[4];
#pragma unroll
    for (int j = 0; j < 4; j++) {
        esA[j] = __floats2half2_rn(sp[      k0 + 2*j], sp[      k0 + 2*j + 1]);
        esB[j] = __floats2half2_rn(sp[36  + k0 + 2*j], sp[36  + k0 + 2*j + 1]);
        esC[j] = __floats2half2_rn(sp[72  + k0 + 2*j], sp[72  + k0 + 2*j + 1]);
    }

    const uint4* texu = reinterpret_cast<const uint4*>(g_tex16);

#pragma unroll
    for (int r = 0; r < 8; r++) {
        const int src = (lane & 24) + r;
        const unsigned po = __shfl_sync(0xffffffffu, packedOff, src);
        const unsigned pw = __shfl_sync(0xffffffffu, wbits, src);
        const int o00 = (int)(po & 0xffffu);
        const int o10 = (int)(po >> 16);
        float swx, swy;
        {
            __half2 wh = *reinterpret_cast<const __half2*>(&pw);
            float2 wf = __half22float2(wh);
            swx = wf.x; swy = wf.y;
        }
        const float wxs = (sub < 4) ? (1.f - swx) : swx;
        const __half2 ay2 = __float2half2_rn(wxs * (1.f - swy));
        const __half2 by2 = __float2half2_rn(wxs * swy);

        const uint4 vy0 = texu[(size_t)o00 * 4 + sub];
        const uint4 vy1 = texu[(size_t)o10 * 4 + sub];
        const __half2* a = reinterpret_cast<const __half2*>(&vy0);
        const __half2* b = reinterpret_cast<const __half2*>(&vy1);

        __half2 r0 = __hfma2(by2, b[0], __hmul2(ay2, a[0]));
        __half2 r1 = __hfma2(by2, b[1], __hmul2(ay2, a[1]));
        __half2 r2 = __hfma2(by2, b[2], __hmul2(ay2, a[2]));
        __half2 r3 = __hfma2(by2, b[3], __hmul2(ay2, a[3]));

        __half2 acc0 = __hmul2(esA[0], r0);
        acc0 = __hfma2(esA[1], r1, acc0);
        acc0 = __hfma2(esA[2], r2, acc0);
        acc0 = __hfma2(esA[3], r3, acc0);
        __half2 acc1 = __hmul2(esB[0], r0);
        acc1 = __hfma2(esB[1], r1, acc1);
        acc1 = __hfma2(esB[2], r2, acc1);
        acc1 = __hfma2(esB[3], r3, acc1);
        __half2 acc2 = __hmul2(esC[0], r0);
        acc2 = __hfma2(esC[1], r1, acc2);
        acc2 = __hfma2(esC[2], r2, acc2);
        acc2 = __hfma2(esC[3], r3, acc2);

        float t0 = __low2float(acc0) + __high2float(acc0);
        float t1 = __low2float(acc1) + __high2float(acc1);
        float t2 = __low2float(acc2) + __high2float(acc2);

        t0 += __shfl_xor_sync(0xffffffffu, t0, 4);
        t1 += __shfl_xor_sync(0xffffffffu, t1, 4);
        t2 += __shfl_xor_sync(0xffffffffu, t2, 4);
        t0 += __shfl_xor_sync(0xffffffffu, t0, 2);
        t1 += __shfl_xor_sync(0xffffffffu, t1, 2);
        t2 += __shfl_xor_sync(0xffffffffu, t2, 2);
        t0 += __shfl_xor_sync(0xffffffffu, t0, 1);
        t1 += __shfl_xor_sync(0xffffffffu, t1, 1);
        t2 += __shfl_xor_sync(0xffffffffu, t2, 1);

        if (sub == r) { d0 += t0; d1 += t1; d2 += t2; }
    }

    // ----- Phase C -----
    const float raw0 = shadeE * d0 + se0;
    const float raw1 = shadeE * d1 + se1;
    const float raw2 = shadeE * d2 + se2;
    const float rr = fmaxf(sp[108] * raw0 + sp[109] * raw1 + sp[110] * raw2, 0.f);
    const float rg = fmaxf(sp[111] * raw0 + sp[112] * raw1 + sp[113] * raw2, 0.f);
    const float rb = fmaxf(sp[114] * raw0 + sp[115] * raw1 + sp[116] * raw2, 0.f);

    const size_t b3 = ((size_t)n * 3) * IMG2 + p;
    o_rgb[b3] = rr; o_rgb[b3 + IMG2] = rg; o_rgb[b3 + 2 * IMG2] = rb;
    o_raw[b3] = raw0; o_raw[b3 + IMG2] = raw1; o_raw[b3 + 2 * IMG2] = raw2;
}

// ---------------------------------------------------------------------------
extern "C" void kernel_launch(void* const* d_in, const int* in_sizes, int n_in,
                              void* d_out, int out_size) {
    const float* lighting  = (const float*)d_in[0];
    const float* mel       = (const float*)d_in[1];
    const float* blood     = (const float*)d_in[2];
    const float* shade     = (const float*)d_in[3];
    const float* spec      = (const float*)d_in[4];
    const float* illA      = (const float*)d_in[5];
    const float* illF      = (const float*)d_in[6];
    const float* pcaMeans  = (const float*)d_in[7];
    const float* pcaComp   = (const float*)d_in[8];
    const float* skinColor = (const float*)d_in[9];
    const float* tmatrix   = (const float*)d_in[10];
    float* out = (float*)d_out;

    int N = in_sizes[0] / 17;            // lighting [N,17]
    size_t NS = (size_t)N * IMG2;
    float* outB = out + 9 * NS;

    k_prep<<<257, 256>>>(skinColor, lighting, illA, illF, pcaMeans,
                         pcaComp, tmatrix, outB, N);
    k_main<<<dim3(16, N), 256>>>(mel, blood, shade, spec, out, N);
}

// round 7
// speedup vs baseline: 2.0149x; 1.0007x over previous
#include <cuda_runtime.h>
#include <cuda_fp16.h>
#include <math.h>

// ---------------------------------------------------------------------------
// Fully fused decoder (1 kernel):
//   blocks 0..255  : transpose skinColor[33,256,256] -> g_tex16 [65536][32] fp16
//                    (64B rows) + g_texE4 quad plane (8B/texel); arrive g_done
//   block 256      : per-image lighting precompute -> g_params, b out; arrive
//   blocks 257..   : main pixels. Phase A0 (LUT/params-independent) first,
//                    then spin-wait g_done==257, then params+gather+outputs.
//   Last main block resets counters (graph-replay deterministic).
// Output layout (flat f32): rgb[N*3*S], shade[N*S], spec[N*3*S], blood[N*S],
//   mel[N*S], b[N*2], raw[N*3*S]   (S=4096)
// ---------------------------------------------------------------------------

#define NPIX   65536
#define IMG2   4096
#define MAXN   256
#define TROW   40   // smem transpose row pitch in halves (80B, 16B-granular)

__device__ __half  g_tex16[(NPIX + 16) * 32];   // 4 MB, 64B per texel row (+pad)
__device__ uint2   g_texE4[NPIX + 16];          // 512 KB quad plane
__device__ float   g_params[MAXN * 128];        // ES[108] G2[9] lc[3]
__device__ int     g_done;                      // prep arrival counter
__device__ int     g_mainDone;                  // main completion counter

__constant__ float c_S0[33] = {94.8f,104.8f,105.9f,96.8f,113.9f,125.6f,125.5f,121.3f,121.3f,113.5f,113.1f,110.8f,106.5f,108.8f,105.3f,104.4f,100.0f,96.0f,95.1f,89.1f,90.5f,90.3f,88.4f,84.0f,85.1f,81.9f,82.6f,84.9f,81.3f,71.9f,74.3f,76.4f,63.3f};
__constant__ float c_S1[33] = {43.4f,46.3f,43.9f,37.1f,36.7f,35.9f,32.6f,27.9f,24.3f,20.1f,16.2f,13.2f,8.6f,6.1f,4.2f,1.9f,0.0f,-1.6f,-3.5f,-3.5f,-5.8f,-7.2f,-8.6f,-9.5f,-10.9f,-10.7f,-12.0f,-14.0f,-13.6f,-12.0f,-13.3f,-12.9f,-10.6f};
__constant__ float c_S2[33] = {-1.1f,-0.5f,-0.7f,-1.2f,-2.6f,-2.9f,-2.8f,-2.6f,-2.6f,-1.8f,-1.5f,-1.3f,-1.2f,-1.0f,-0.5f,-0.3f,0.0f,0.2f,0.5f,2.1f,3.2f,4.1f,4.7f,5.1f,6.7f,7.3f,8.6f,9.8f,10.2f,8.3f,9.6f,8.5f,7.0f};
__constant__ float c_X[9]  = {3.2406f,-1.537f,-0.498f,-0.968f,1.8758f,0.0415f,0.0557f,-0.204f,1.057f};

__device__ __forceinline__ void precompute_image(
    int n, const float* lp, const float* illA, const float* illF,
    const float* pcaMeans, const float* pcaComp, const float* tmat,
    float* outB)
{
    float mx = lp[0];
#pragma unroll
    for (int j = 1; j < 14; j++) mx = fmaxf(mx, lp[j]);
    float w[14], wsum = 0.f;
#pragma unroll
    for (int j = 0; j < 14; j++) { w[j] = expf(lp[j] - mx); wsum += w[j]; }
    float winv = 1.f / wsum;
    float wA = w[0] * winv, wD = w[1] * winv;
    float fw[12];
#pragma unroll
    for (int j = 0; j < 12; j++) fw[j] = w[j + 2] * winv;

    float colorTemp = 1.f / (1.f + expf(-lp[14]));
    float b0 = 6.f / (1.f + expf(-lp[15])) - 3.f;
    float b1 = 6.f / (1.f + expf(-lp[16])) - 3.f;
    outB[2 * n] = b0; outB[2 * n + 1] = b1;

    float t = colorTemp * 21000.f + 4000.f;
    float it = 1.f / t;
    float x = (t <= 7000.f)
        ? ((-4607000000.f * it + 2967800.f) * it + 99.11f) * it + 0.244063f
        : ((-2006400000.f * it + 1901800.f) * it + 247.48f) * it + 0.23704f;
    float y  = -3.f * x * x + 2.87f * x - 0.275f;
    float m  = 0.0241f + 0.2562f * x - 0.7341f * y;
    float m1 = (-1.3515f - 1.7703f * x + 5.9114f * y) / m;
    float m2 = (0.03f - 31.4424f * x + 30.0717f * y) / m;
    float s[33]; float ssum = 0.f;
#pragma unroll
    for (int k = 0; k < 33; k++) { s[k] = c_S0[k] + m1 * c_S1[k] + m2 * c_S2[k]; ssum += s[k]; }
    float sinv = 1.f / ssum;

    float e[33]; float esum = 0.f;
    for (int k = 0; k < 33; k++) {
        float ef = 0.f;
#pragma unroll
        for (int j = 0; j < 12; j++) ef += fw[j] * illF[k * 12 + j];
        float ev = wA * illA[k] + wD * s[k] * sinv + ef;
        e[k] = ev; esum += ev;
    }
    float einv = 1.f / esum;

    float lc[3] = {0.f, 0.f, 0.f};
    float* P = g_params + (size_t)n * 128;
    for (int c = 0; c < 3; c++) {
        for (int k = 0; k < 33; k++) {
            int i = c * 33 + k;
            float Sv = fmaxf(b0 * pcaComp[2 * i] + b1 * pcaComp[2 * i + 1] + pcaMeans[i], 0.f);
            lc[c] += Sv;
            P[c * 36 + k] = e[k] * einv * Sv;
        }
        P[c * 36 + 33] = 0.f; P[c * 36 + 34] = 0.f; P[c * 36 + 35] = 0.f;
    }

    float tx = (b0 * (1.f / 3.f) + 1.f) * 0.5f * 127.f;
    float ty = (b1 * (1.f / 3.f) + 1.f) * 0.5f * 127.f;
    float fx0 = floorf(tx), fy0 = floorf(ty);
    float wx = tx - fx0, wy = ty - fy0;
    int x0 = min(max((int)fx0, 0), 127), y0 = min(max((int)fy0, 0), 127);
    int x1 = min(x0 + 1, 127),           y1 = min(y0 + 1, 127);
    float w00 = (1.f - wx) * (1.f - wy), w01 = wx * (1.f - wy);
    float w10 = (1.f - wx) * wy,         w11 = wx * wy;
    float T[9];
#pragma unroll
    for (int ch = 0; ch < 9; ch++) {
        const float* tp = tmat + (size_t)ch * 128 * 128;
        T[ch] = w00 * tp[y0 * 128 + x0] + w01 * tp[y0 * 128 + x1]
              + w10 * tp[y1 * 128 + x0] + w11 * tp[y1 * 128 + x1];
    }
    for (int o = 0; o < 3; o++)
        for (int c = 0; c < 3; c++) {
            float g = c_X[o * 3 + 0] * T[c * 3 + 0]
                    + c_X[o * 3 + 1] * T[c * 3 + 1]
                    + c_X[o * 3 + 2] * T[c * 3 + 2];
            P[108 + o * 3 + c] = g / lc[c];
        }
    P[117] = lc[0]; P[118] = lc[1]; P[119] = lc[2];
}

// ---------------------------------------------------------------------------
__global__ void __launch_bounds__(256, 4) k_fused(
    const float* __restrict__ sc,
    const float* __restrict__ lighting, const float* __restrict__ illA,
    const float* __restrict__ illF, const float* __restrict__ pcaMeans,
    const float* __restrict__ pcaComp, const float* __restrict__ tmat,
    const float* __restrict__ mel, const float* __restrict__ blood,
    const float* __restrict__ shade, const float* __restrict__ spec,
    float* __restrict__ out, int N)
{
    __shared__ __align__(16) __half tile[256 * TROW];   // 20 KB (prep branch)
    __shared__ float sp[120];

    const int bid = blockIdx.x;
    const int tid = threadIdx.x;

    // ===================== producer: transpose =====================
    if (bid < 256) {
        const int base = bid * 256;
        const int p = base + tid;

        // E-plane quad (clamped indices; clamped entries never weighted)
        const float* sc32 = sc + (size_t)32 * NPIX;
        const int pn  = min(p + 1,   NPIX - 1);
        const int pd  = min(p + 256, NPIX - 1);
        const int pdn = min(p + 257, NPIX - 1);
        {
            __half2 top = __floats2half2_rn(sc32[p],  sc32[pn]);
            __half2 bot = __floats2half2_rn(sc32[pd], sc32[pdn]);
            uint2 u;
            u.x = *reinterpret_cast<unsigned*>(&top);
            u.y = *reinterpret_cast<unsigned*>(&bot);
            g_texE4[p] = u;
        }

        // two 16-channel batches (MLP=16, fits 64-reg cap)
#pragma unroll
        for (int h = 0; h < 2; h++) {
            float v[16];
#pragma unroll
            for (int c = 0; c < 16; c++) v[c] = sc[(size_t)(h * 16 + c) * NPIX + p];
#pragma unroll
            for (int c = 0; c < 16; c++)
                tile[tid * TROW + h * 16 + c] = __float2half_rn(v[c]);
        }
        __syncthreads();

        // packed coalesced row writes: 1024 uint4 per block, 4 per thread
        uint4* dst = reinterpret_cast<uint4*>(g_tex16) + (size_t)base * 4;
#pragma unroll
        for (int j = 0; j < 4; j++) {
            int i = tid + 256 * j;
            int texel = i >> 2, part = i & 3;
            const uint4* srcu = reinterpret_cast<const uint4*>(tile + texel * TROW) + part;
            dst[(size_t)texel * 4 + part] = *srcu;
        }
        __threadfence();
        __syncthreads();
        if (tid == 0) atomicAdd(&g_done, 1);
        return;
    }

    // ===================== producer: precompute =====================
    const size_t NS = (size_t)N * IMG2;
    if (bid == 256) {
        float* outB = out + 9 * NS;
        if (tid < N)
            precompute_image(tid, lighting + (size_t)tid * 17, illA, illF,
                             pcaMeans, pcaComp, tmat, outB);
        __threadfence();
        __syncthreads();
        if (tid == 0) atomicAdd(&g_done, 1);
        return;
    }

    // ===================== consumer: main pixels =====================
    const int mb   = bid - 257;
    const int n    = mb >> 4;
    const int lane = tid & 31;
    const int sub  = lane & 7;
    const int p    = (mb & 15) * 256 + tid;

    float* o_rgb   = out;
    float* o_shade = out + 3 * NS;
    float* o_spec  = out + 4 * NS;
    float* o_blood = out + 7 * NS;
    float* o_mel   = out + 8 * NS;
    float* o_raw   = out + 9 * NS + 2 * (size_t)N;

    // ----- Phase A0: LUT/params-independent -----
    const size_t idx = (size_t)n * IMG2 + p;
    const float mv = mel[idx], bv = blood[idx], sv = shade[idx];
    const float sv0 = spec[((size_t)n * 3 + 0) * IMG2 + p];
    const float sv1 = spec[((size_t)n * 3 + 1) * IMG2 + p];
    const float sv2 = spec[((size_t)n * 3 + 2) * IMG2 + p];

    const float ms = 2.f / (1.f + __expf(-mv)) - 1.f;
    const float bs = 2.f / (1.f + __expf(-bv)) - 1.f;

    const float tx = (ms + 1.f) * 127.5f;
    const float ty = (bs + 1.f) * 127.5f;
    const float fx0 = floorf(tx), fy0 = floorf(ty);
    float wx = tx - fx0, wy = ty - fy0;
    const int x0 = min(max((int)fx0, 0), 255);
    const int y0 = min(max((int)fy0, 0), 255);
    const int y1 = min(y0 + 1, 255);
    const int off00 = y0 * 256 + x0;     // < 65536
    const int off10 = y1 * 256 + x0;     // < 65536

    const float w00 = (1.f - wx) * (1.f - wy), w01 = wx * (1.f - wy);
    const float w10 = (1.f - wx) * wy,         w11 = wx * wy;

    const float shadeE = __expf(sv);
    const float ex0 = __expf(sv0);
    const float ex1 = __expf(sv1);
    const float ex2 = __expf(sv2);

    o_mel[idx]   = ms;
    o_blood[idx] = bs;
    o_shade[idx] = shadeE;

    const unsigned packedOff = (unsigned)off00 | ((unsigned)off10 << 16);
    unsigned wbits;
    {
        __half2 wpack = __floats2half2_rn(wx, wy);
        wbits = *reinterpret_cast<unsigned*>(&wpack);
    }

    // ----- wait for producers -----
    if (tid == 0) {
        while (atomicAdd(&g_done, 0) < 257) __nanosleep(64);
    }
    __syncthreads();

    if (tid < 120) sp[tid] = g_params[(size_t)n * 128 + tid];
    __syncthreads();

    // ----- params-dependent elementwise -----
    const float se0 = ex0 * sp[117];
    const float se1 = ex1 * sp[118];
    const float se2 = ex2 * sp[119];
    {
        const size_t b3 = ((size_t)n * 3) * IMG2 + p;
        o_spec[b3] = se0; o_spec[b3 + IMG2] = se1; o_spec[b3 + 2 * IMG2] = se2;
    }

    // channel-32: one 8B quad load per pixel
    float er;
    {
        uint2 u = g_texE4[off00];
        __half2 th = *reinterpret_cast<__half2*>(&u.x);
        __half2 bh = *reinterpret_cast<__half2*>(&u.y);
        float2 tf = __half22float2(th);
        float2 bf = __half22float2(bh);
        er = w00 * tf.x + w01 * tf.y + w10 * bf.x + w11 * bf.y;
    }
    float d0 = sp[32]  * er;
    float d1 = sp[68]  * er;
    float d2 = sp[104] * er;

    // ----- cooperative gather -----
    const int k0 = (sub & 3) * 8;
    __half2 esA[4], esB[4], esC[4];
#pragma unroll
    for (int j = 0; j < 4; j++) {
        esA[j] = __floats2half2_rn(sp[      k0 + 2*j], sp[      k0 + 2*j + 1]);
        esB[j] = __floats2half2_rn(sp[36  + k0 + 2*j], sp[36  + k0 + 2*j + 1]);
        esC[j] = __floats2half2_rn(sp[72  + k0 + 2*j], sp[72  + k0 + 2*j + 1]);
    }

    const uint4* texu = reinterpret_cast<const uint4*>(g_tex16);

#pragma unroll
    for (int r = 0; r < 8; r++) {
        const int src = (lane & 24) + r;
        const unsigned po = __shfl_sync(0xffffffffu, packedOff, src);
        const unsigned pw = __shfl_sync(0xffffffffu, wbits, src);
        const int o00 = (int)(po & 0xffffu);
        const int o10 = (int)(po >> 16);
        float swx, swy;
        {
            __half2 wh = *reinterpret_cast<const __half2*>(&pw);
            float2 wf = __half22float2(wh);
            swx = wf.x; swy = wf.y;
        }
        const float wxs = (sub < 4) ? (1.f - swx) : swx;
        const __half2 ay2 = __float2half2_rn(wxs * (1.f - swy));
        const __half2 by2 = __float2half2_rn(wxs * swy);

        const uint4 vy0 = texu[(size_t)o00 * 4 + sub];
        const uint4 vy1 = texu[(size_t)o10 * 4 + sub];
        const __half2* a = reinterpret_cast<const __half2*>(&vy0);
        const __half2* b = reinterpret_cast<const __half2*>(&vy1);

        __half2 r0 = __hfma2(by2, b[0], __hmul2(ay2, a[0]));
        __half2 r1 = __hfma2(by2, b[1], __hmul2(ay2, a[1]));
        __half2 r2 = __hfma2(by2, b[2], __hmul2(ay2, a[2]));
        __half2 r3 = __hfma2(by2, b[3], __hmul2(ay2, a[3]));

        __half2 acc0 = __hmul2(esA[0], r0);
        acc0 = __hfma2(esA[1], r1, acc0);
        acc0 = __hfma2(esA[2], r2, acc0);
        acc0 = __hfma2(esA[3], r3, acc0);
        __half2 acc1 = __hmul2(esB[0], r0);
        acc1 = __hfma2(esB[1], r1, acc1);
        acc1 = __hfma2(esB[2], r2, acc1);
        acc1 = __hfma2(esB[3], r3, acc1);
        __half2 acc2 = __hmul2(esC[0], r0);
        acc2 = __hfma2(esC[1], r1, acc2);
        acc2 = __hfma2(esC[2], r2, acc2);
        acc2 = __hfma2(esC[3], r3, acc2);

        // pack (t0,t1) into one half2 butterfly; t2 in fp32
        __half2 t01 = __halves2half2(
            __hadd(__low2half(acc0), __high2half(acc0)),
            __hadd(__low2half(acc1), __high2half(acc1)));
        float t2 = __low2float(acc2) + __high2float(acc2);

        unsigned u01 = *reinterpret_cast<unsigned*>(&t01);
        {
            unsigned o = __shfl_xor_sync(0xffffffffu, u01, 4);
            __half2 hv = __hadd2(*reinterpret_cast<__half2*>(&u01),
                                 *reinterpret_cast<__half2*>(&o));
            u01 = *reinterpret_cast<unsigned*>(&hv);
        }
        t2 += __shfl_xor_sync(0xffffffffu, t2, 4);
        {
            unsigned o = __shfl_xor_sync(0xffffffffu, u01, 2);
            __half2 hv = __hadd2(*reinterpret_cast<__half2*>(&u01),
                                 *reinterpret_cast<__half2*>(&o));
            u01 = *reinterpret_cast<unsigned*>(&hv);
        }
        t2 += __shfl_xor_sync(0xffffffffu, t2, 2);
        {
            unsigned o = __shfl_xor_sync(0xffffffffu, u01, 1);
            __half2 hv = __hadd2(*reinterpret_cast<__half2*>(&u01),
                                 *reinterpret_cast<__half2*>(&o));
            u01 = *reinterpret_cast<unsigned*>(&hv);
        }
        t2 += __shfl_xor_sync(0xffffffffu, t2, 1);

        if (sub == r) {
            __half2 hv = *reinterpret_cast<__half2*>(&u01);
            d0 += __low2float(hv);
            d1 += __high2float(hv);
            d2 += t2;
        }
    }

    // ----- finish -----
    const float raw0 = shadeE * d0 + se0;
    const float raw1 = shadeE * d1 + se1;
    const float raw2 = shadeE * d2 + se2;
    const float rr = fmaxf(sp[108] * raw0 + sp[109] * raw1 + sp[110] * raw2, 0.f);
    const float rg = fmaxf(sp[111] * raw0 + sp[112] * raw1 + sp[113] * raw2, 0.f);
    const float rb = fmaxf(sp[114] * raw0 + sp[115] * raw1 + sp[116] * raw2, 0.f);

    const size_t b3 = ((size_t)n * 3) * IMG2 + p;
    o_rgb[b3] = rr; o_rgb[b3 + IMG2] = rg; o_rgb[b3 + 2 * IMG2] = rb;
    o_raw[b3] = raw0; o_raw[b3 + IMG2] = raw1; o_raw[b3 + 2 * IMG2] = raw2;

    // ----- replay-safe counter reset by last main block -----
    __syncthreads();
    if (tid == 0) {
        int old = atomicAdd(&g_mainDone, 1);
        if (old == 16 * N - 1) {
            g_done = 0;
            g_mainDone = 0;
            __threadfence();
        }
    }
}

// ---------------------------------------------------------------------------
extern "C" void kernel_launch(void* const* d_in, const int* in_sizes, int n_in,
                              void* d_out, int out_size) {
    const float* lighting  = (const float*)d_in[0];
    const float* mel       = (const float*)d_in[1];
    const float* blood     = (const float*)d_in[2];
    const float* shade     = (const float*)d_in[3];
    const float* spec      = (const float*)d_in[4];
    const float* illA      = (const float*)d_in[5];
    const float* illF      = (const float*)d_in[6];
    const float* pcaMeans  = (const float*)d_in[7];
    const float* pcaComp   = (const float*)d_in[8];
    const float* skinColor = (const float*)d_in[9];
    const float* tmatrix   = (const float*)d_in[10];
    float* out = (float*)d_out;

    int N = in_sizes[0] / 17;            // lighting [N,17]
    int blocks = 257 + 16 * N;

    k_fused<<<blocks, 256>>>(skinColor, lighting, illA, illF, pcaMeans,
                             pcaComp, tmatrix, mel, blood, shade, spec,
                             out, N);
}

// round 8
// speedup vs baseline: 2.0315x; 1.0082x over previous
#include <cuda_runtime.h>
#include <cuda_fp16.h>
#include <math.h>

// ---------------------------------------------------------------------------
// Fully fused decoder (1 kernel):
//   block 0        : per-image lighting precompute -> g_params, b out; arrive
//   blocks 1..1024 : transpose skinColor[33,256,256] -> g_tex16 [65536][32] fp16
//                    (64 texels/block, coalesced) + g_texE4 quad plane; arrive
//   blocks 1025..  : main pixels. Phase A0 (LUT/params-independent) first,
//                    then spin-wait g_done==1025, then params+gather+outputs.
//   Last main block resets counters (graph-replay deterministic).
// Output layout (flat f32): rgb[N*3*S], shade[N*S], spec[N*3*S], blood[N*S],
//   mel[N*S], b[N*2], raw[N*3*S]   (S=4096)
// ---------------------------------------------------------------------------

#define NPIX    65536
#define IMG2    4096
#define MAXN    256
#define TROW    40          // smem transpose row pitch in halves (80B)
#define NPROD   1025        // 1 precompute + 1024 transpose blocks

__device__ __half  g_tex16[(NPIX + 16) * 32];   // 4 MB, 64B per texel row (+pad)
__device__ uint2   g_texE4[NPIX + 16];          // 512 KB quad plane
__device__ float   g_params[MAXN * 128];        // ES[108] G2[9] lc[3]
__device__ int     g_done;                      // prep arrival counter
__device__ int     g_mainDone;                  // main completion counter

__constant__ float c_S0[33] = {94.8f,104.8f,105.9f,96.8f,113.9f,125.6f,125.5f,121.3f,121.3f,113.5f,113.1f,110.8f,106.5f,108.8f,105.3f,104.4f,100.0f,96.0f,95.1f,89.1f,90.5f,90.3f,88.4f,84.0f,85.1f,81.9f,82.6f,84.9f,81.3f,71.9f,74.3f,76.4f,63.3f};
__constant__ float c_S1[33] = {43.4f,46.3f,43.9f,37.1f,36.7f,35.9f,32.6f,27.9f,24.3f,20.1f,16.2f,13.2f,8.6f,6.1f,4.2f,1.9f,0.0f,-1.6f,-3.5f,-3.5f,-5.8f,-7.2f,-8.6f,-9.5f,-10.9f,-10.7f,-12.0f,-14.0f,-13.6f,-12.0f,-13.3f,-12.9f,-10.6f};
__constant__ float c_S2[33] = {-1.1f,-0.5f,-0.7f,-1.2f,-2.6f,-2.9f,-2.8f,-2.6f,-2.6f,-1.8f,-1.5f,-1.3f,-1.2f,-1.0f,-0.5f,-0.3f,0.0f,0.2f,0.5f,2.1f,3.2f,4.1f,4.7f,5.1f,6.7f,7.3f,8.6f,9.8f,10.2f,8.3f,9.6f,8.5f,7.0f};
__constant__ float c_X[9]  = {3.2406f,-1.537f,-0.498f,-0.968f,1.8758f,0.0415f,0.0557f,-0.204f,1.057f};

__device__ __forceinline__ void precompute_image(
    int n, const float* lp, const float* illA, const float* illF,
    const float* pcaMeans, const float* pcaComp, const float* tmat,
    float* outB)
{
    float mx = lp[0];
#pragma unroll
    for (int j = 1; j < 14; j++) mx = fmaxf(mx, lp[j]);
    float w[14], wsum = 0.f;
#pragma unroll
    for (int j = 0; j < 14; j++) { w[j] = expf(lp[j] - mx); wsum += w[j]; }
    float winv = 1.f / wsum;
    float wA = w[0] * winv, wD = w[1] * winv;
    float fw[12];
#pragma unroll
    for (int j = 0; j < 12; j++) fw[j] = w[j + 2] * winv;

    float colorTemp = 1.f / (1.f + expf(-lp[14]));
    float b0 = 6.f / (1.f + expf(-lp[15])) - 3.f;
    float b1 = 6.f / (1.f + expf(-lp[16])) - 3.f;
    outB[2 * n] = b0; outB[2 * n + 1] = b1;

    float t = colorTemp * 21000.f + 4000.f;
    float it = 1.f / t;
    float x = (t <= 7000.f)
        ? ((-4607000000.f * it + 2967800.f) * it + 99.11f) * it + 0.244063f
        : ((-2006400000.f * it + 1901800.f) * it + 247.48f) * it + 0.23704f;
    float y  = -3.f * x * x + 2.87f * x - 0.275f;
    float m  = 0.0241f + 0.2562f * x - 0.7341f * y;
    float m1 = (-1.3515f - 1.7703f * x + 5.9114f * y) / m;
    float m2 = (0.03f - 31.4424f * x + 30.0717f * y) / m;
    float s[33]; float ssum = 0.f;
#pragma unroll
    for (int k = 0; k < 33; k++) { s[k] = c_S0[k] + m1 * c_S1[k] + m2 * c_S2[k]; ssum += s[k]; }
    float sinv = 1.f / ssum;

    float e[33]; float esum = 0.f;
    for (int k = 0; k < 33; k++) {
        float ef = 0.f;
#pragma unroll
        for (int j = 0; j < 12; j++) ef += fw[j] * illF[k * 12 + j];
        float ev = wA * illA[k] + wD * s[k] * sinv + ef;
        e[k] = ev; esum += ev;
    }
    float einv = 1.f / esum;

    float lc[3] = {0.f, 0.f, 0.f};
    float* P = g_params + (size_t)n * 128;
    for (int c = 0; c < 3; c++) {
        for (int k = 0; k < 33; k++) {
            int i = c * 33 + k;
            float Sv = fmaxf(b0 * pcaComp[2 * i] + b1 * pcaComp[2 * i + 1] + pcaMeans[i], 0.f);
            lc[c] += Sv;
            P[c * 36 + k] = e[k] * einv * Sv;
        }
        P[c * 36 + 33] = 0.f; P[c * 36 + 34] = 0.f; P[c * 36 + 35] = 0.f;
    }

    float tx = (b0 * (1.f / 3.f) + 1.f) * 0.5f * 127.f;
    float ty = (b1 * (1.f / 3.f) + 1.f) * 0.5f * 127.f;
    float fx0 = floorf(tx), fy0 = floorf(ty);
    float wx = tx - fx0, wy = ty - fy0;
    int x0 = min(max((int)fx0, 0), 127), y0 = min(max((int)fy0, 0), 127);
    int x1 = min(x0 + 1, 127),           y1 = min(y0 + 1, 127);
    float w00 = (1.f - wx) * (1.f - wy), w01 = wx * (1.f - wy);
    float w10 = (1.f - wx) * wy,         w11 = wx * wy;
    float T[9];
#pragma unroll
    for (int ch = 0; ch < 9; ch++) {
        const float* tp = tmat + (size_t)ch * 128 * 128;
        T[ch] = w00 * tp[y0 * 128 + x0] + w01 * tp[y0 * 128 + x1]
              + w10 * tp[y1 * 128 + x0] + w11 * tp[y1 * 128 + x1];
    }
    for (int o = 0; o < 3; o++)
        for (int c = 0; c < 3; c++) {
            float g = c_X[o * 3 + 0] * T[c * 3 + 0]
                    + c_X[o * 3 + 1] * T[c * 3 + 1]
                    + c_X[o * 3 + 2] * T[c * 3 + 2];
            P[108 + o * 3 + c] = g / lc[c];
        }
    P[117] = lc[0]; P[118] = lc[1]; P[119] = lc[2];
}

// ---------------------------------------------------------------------------
__global__ void __launch_bounds__(256, 4) k_fused(
    const float* __restrict__ sc,
    const float* __restrict__ lighting, const float* __restrict__ illA,
    const float* __restrict__ illF, const float* __restrict__ pcaMeans,
    const float* __restrict__ pcaComp, const float* __restrict__ tmat,
    const float* __restrict__ mel, const float* __restrict__ blood,
    const float* __restrict__ shade, const float* __restrict__ spec,
    float* __restrict__ out, int N)
{
    __shared__ __align__(16) __half tile[64 * TROW];   // 5 KB (transpose branch)
    __shared__ float sp[120];

    const int bid = blockIdx.x;
    const int tid = threadIdx.x;
    const size_t NS = (size_t)N * IMG2;

    // ===================== producer: precompute (bid 0, wave-1) ==============
    if (bid == 0) {
        float* outB = out + 9 * NS;
        if (tid < N)
            precompute_image(tid, lighting + (size_t)tid * 17, illA, illF,
                             pcaMeans, pcaComp, tmat, outB);
        __threadfence();
        __syncthreads();
        if (tid == 0) atomicAdd(&g_done, 1);
        return;
    }

    // ===================== producer: transpose (bids 1..1024) ================
    if (bid < NPROD) {
        const int base   = (bid - 1) * 64;     // 64 texels per block
        const int texl   = tid & 63;           // local texel 0..63
        const int part   = tid >> 6;           // channel octet 0..3
        const int p      = base + texl;

        // 8 coalesced channel reads (64 consecutive texels per warp-pair)
        float v[8];
#pragma unroll
        for (int c = 0; c < 8; c++) v[c] = sc[(size_t)(part * 8 + c) * NPIX + p];
#pragma unroll
        for (int c = 0; c < 8; c++)
            tile[texl * TROW + part * 8 + c] = __float2half_rn(v[c]);

        // E-plane quad (one octet-group handles it)
        if (part == 0) {
            const float* sc32 = sc + (size_t)32 * NPIX;
            const int pn  = min(p + 1,   NPIX - 1);
            const int pd  = min(p + 256, NPIX - 1);
            const int pdn = min(p + 257, NPIX - 1);
            __half2 top = __floats2half2_rn(sc32[p],  sc32[pn]);
            __half2 bot = __floats2half2_rn(sc32[pd], sc32[pdn]);
            uint2 u;
            u.x = *reinterpret_cast<unsigned*>(&top);
            u.y = *reinterpret_cast<unsigned*>(&bot);
            g_texE4[p] = u;
        }
        __syncthreads();

        // contiguous 4 KB row write: 256 uint4, one per thread
        uint4* dst = reinterpret_cast<uint4*>(g_tex16) + (size_t)base * 4;
        const int texw = tid >> 2, pw = tid & 3;
        dst[(size_t)texw * 4 + pw] =
            reinterpret_cast<const uint4*>(tile + texw * TROW)[pw];

        __threadfence();
        __syncthreads();
        if (tid == 0) atomicAdd(&g_done, 1);
        return;
    }

    // ===================== consumer: main pixels =============================
    const int mb   = bid - NPROD;
    const int n    = mb >> 4;
    const int lane = tid & 31;
    const int sub  = lane & 7;
    const int p    = (mb & 15) * 256 + tid;

    float* o_rgb   = out;
    float* o_shade = out + 3 * NS;
    float* o_spec  = out + 4 * NS;
    float* o_blood = out + 7 * NS;
    float* o_mel   = out + 8 * NS;
    float* o_raw   = out + 9 * NS + 2 * (size_t)N;

    // ----- Phase A0: LUT/params-independent -----
    const size_t idx = (size_t)n * IMG2 + p;
    const float mv = mel[idx], bv = blood[idx], sv = shade[idx];
    const float sv0 = spec[((size_t)n * 3 + 0) * IMG2 + p];
    const float sv1 = spec[((size_t)n * 3 + 1) * IMG2 + p];
    const float sv2 = spec[((size_t)n * 3 + 2) * IMG2 + p];

    const float ms = 2.f / (1.f + __expf(-mv)) - 1.f;
    const float bs = 2.f / (1.f + __expf(-bv)) - 1.f;

    const float tx = (ms + 1.f) * 127.5f;
    const float ty = (bs + 1.f) * 127.5f;
    const float fx0 = floorf(tx), fy0 = floorf(ty);
    float wx = tx - fx0, wy = ty - fy0;
    const int x0 = min(max((int)fx0, 0), 255);
    const int y0 = min(max((int)fy0, 0), 255);
    const int y1 = min(y0 + 1, 255);
    const int off00 = y0 * 256 + x0;     // < 65536
    const int off10 = y1 * 256 + x0;     // < 65536

    const float w00 = (1.f - wx) * (1.f - wy), w01 = wx * (1.f - wy);
    const float w10 = (1.f - wx) * wy,         w11 = wx * wy;

    const float shadeE = __expf(sv);
    const float ex0 = __expf(sv0);
    const float ex1 = __expf(sv1);
    const float ex2 = __expf(sv2);

    o_mel[idx]   = ms;
    o_blood[idx] = bs;
    o_shade[idx] = shadeE;

    const unsigned packedOff = (unsigned)off00 | ((unsigned)off10 << 16);
    unsigned wbits;
    {
        __half2 wpack = __floats2half2_rn(wx, wy);
        wbits = *reinterpret_cast<unsigned*>(&wpack);
    }

    // ----- wait for producers -----
    if (tid == 0) {
        while (*(volatile int*)&g_done < NPROD) __nanosleep(64);
    }
    __syncthreads();

    if (tid < 120) sp[tid] = g_params[(size_t)n * 128 + tid];
    __syncthreads();

    // ----- params-dependent elementwise -----
    const float se0 = ex0 * sp[117];
    const float se1 = ex1 * sp[118];
    const float se2 = ex2 * sp[119];
    {
        const size_t b3 = ((size_t)n * 3) * IMG2 + p;
        o_spec[b3] = se0; o_spec[b3 + IMG2] = se1; o_spec[b3 + 2 * IMG2] = se2;
    }

    // channel-32: one 8B quad load per pixel
    float er;
    {
        uint2 u = g_texE4[off00];
        __half2 th = *reinterpret_cast<__half2*>(&u.x);
        __half2 bh = *reinterpret_cast<__half2*>(&u.y);
        float2 tf = __half22float2(th);
        float2 bf = __half22float2(bh);
        er = w00 * tf.x + w01 * tf.y + w10 * bf.x + w11 * bf.y;
    }
    float d0 = sp[32]  * er;
    float d1 = sp[68]  * er;
    float d2 = sp[104] * er;

    // ----- cooperative gather -----
    const int k0 = (sub & 3) * 8;
    __half2 esA[4], esB[4], esC[4];
#pragma unroll
    for (int j = 0; j < 4; j++) {
        esA[j] = __floats2half2_rn(sp[      k0 + 2*j], sp[      k0 + 2*j + 1]);
        esB[j] = __floats2half2_rn(sp[36  + k0 + 2*j], sp[36  + k0 + 2*j + 1]);
        esC[j] = __floats2half2_rn(sp[72  + k0 + 2*j], sp[72  + k0 + 2*j + 1]);
    }

    const uint4* texu = reinterpret_cast<const uint4*>(g_tex16);

#pragma unroll
    for (int r = 0; r < 8; r++) {
        const int src = (lane & 24) + r;
        const unsigned po = __shfl_sync(0xffffffffu, packedOff, src);
        const unsigned pw = __shfl_sync(0xffffffffu, wbits, src);
        const int o00 = (int)(po & 0xffffu);
        const int o10 = (int)(po >> 16);
        float swx, swy;
        {
            __half2 wh = *reinterpret_cast<const __half2*>(&pw);
            float2 wf = __half22float2(wh);
            swx = wf.x; swy = wf.y;
        }
        const float wxs = (sub < 4) ? (1.f - swx) : swx;
        const __half2 ay2 = __float2half2_rn(wxs * (1.f - swy));
        const __half2 by2 = __float2half2_rn(wxs * swy);

        const uint4 vy0 = texu[(size_t)o00 * 4 + sub];
        const uint4 vy1 = texu[(size_t)o10 * 4 + sub];
        const __half2* a = reinterpret_cast<const __half2*>(&vy0);
        const __half2* b = reinterpret_cast<const __half2*>(&vy1);

        __half2 r0 = __hfma2(by2, b[0], __hmul2(ay2, a[0]));
        __half2 r1 = __hfma2(by2, b[1], __hmul2(ay2, a[1]));
        __half2 r2 = __hfma2(by2, b[2], __hmul2(ay2, a[2]));
        __half2 r3 = __hfma2(by2, b[3], __hmul2(ay2, a[3]));

        __half2 acc0 = __hmul2(esA[0], r0);
        acc0 = __hfma2(esA[1], r1, acc0);
        acc0 = __hfma2(esA[2], r2, acc0);
        acc0 = __hfma2(esA[3], r3, acc0);
        __half2 acc1 = __hmul2(esB[0], r0);
        acc1 = __hfma2(esB[1], r1, acc1);
        acc1 = __hfma2(esB[2], r2, acc1);
        acc1 = __hfma2(esB[3], r3, acc1);
        __half2 acc2 = __hmul2(esC[0], r0);
        acc2 = __hfma2(esC[1], r1, acc2);
        acc2 = __hfma2(esC[2], r2, acc2);
        acc2 = __hfma2(esC[3], r3, acc2);

        __half2 t01 = __halves2half2(
            __hadd(__low2half(acc0), __high2half(acc0)),
            __hadd(__low2half(acc1), __high2half(acc1)));
        float t2 = __low2float(acc2) + __high2float(acc2);

        unsigned u01 = *reinterpret_cast<unsigned*>(&t01);
        {
            unsigned o = __shfl_xor_sync(0xffffffffu, u01, 4);
            __half2 hv = __hadd2(*reinterpret_cast<__half2*>(&u01),
                                 *reinterpret_cast<__half2*>(&o));
            u01 = *reinterpret_cast<unsigned*>(&hv);
        }
        t2 += __shfl_xor_sync(0xffffffffu, t2, 4);
        {
            unsigned o = __shfl_xor_sync(0xffffffffu, u01, 2);
            __half2 hv = __hadd2(*reinterpret_cast<__half2*>(&u01),
                                 *reinterpret_cast<__half2*>(&o));
            u01 = *reinterpret_cast<unsigned*>(&hv);
        }
        t2 += __shfl_xor_sync(0xffffffffu, t2, 2);
        {
            unsigned o = __shfl_xor_sync(0xffffffffu, u01, 1);
            __half2 hv = __hadd2(*reinterpret_cast<__half2*>(&u01),
                                 *reinterpret_cast<__half2*>(&o));
            u01 = *reinterpret_cast<unsigned*>(&hv);
        }
        t2 += __shfl_xor_sync(0xffffffffu, t2, 1);

        if (sub == r) {
            __half2 hv = *reinterpret_cast<__half2*>(&u01);
            d0 += __low2float(hv);
            d1 += __high2float(hv);
            d2 += t2;
        }
    }

    // ----- finish -----
    const float raw0 = shadeE * d0 + se0;
    const float raw1 = shadeE * d1 + se1;
    const float raw2 = shadeE * d2 + se2;
    const float rr = fmaxf(sp[108] * raw0 + sp[109] * raw1 + sp[110] * raw2, 0.f);
    const float rg = fmaxf(sp[111] * raw0 + sp[112] * raw1 + sp[113] * raw2, 0.f);
    const float rb = fmaxf(sp[114] * raw0 + sp[115] * raw1 + sp[116] * raw2, 0.f);

    const size_t b3 = ((size_t)n * 3) * IMG2 + p;
    o_rgb[b3] = rr; o_rgb[b3 + IMG2] = rg; o_rgb[b3 + 2 * IMG2] = rb;
    o_raw[b3] = raw0; o_raw[b3 + IMG2] = raw1; o_raw[b3 + 2 * IMG2] = raw2;

    // ----- replay-safe counter reset by last main block -----
    __syncthreads();
    if (tid == 0) {
        int old = atomicAdd(&g_mainDone, 1);
        if (old == 16 * N - 1) {
            g_done = 0;
            g_mainDone = 0;
            __threadfence();
        }
    }
}

// ---------------------------------------------------------------------------
extern "C" void kernel_launch(void* const* d_in, const int* in_sizes, int n_in,
                              void* d_out, int out_size) {
    const float* lighting  = (const float*)d_in[0];
    const float* mel       = (const float*)d_in[1];
    const float* blood     = (const float*)d_in[2];
    const float* shade     = (const float*)d_in[3];
    const float* spec      = (const float*)d_in[4];
    const float* illA      = (const float*)d_in[5];
    const float* illF      = (const float*)d_in[6];
    const float* pcaMeans  = (const float*)d_in[7];
    const float* pcaComp   = (const float*)d_in[8];
    const float* skinColor = (const float*)d_in[9];
    const float* tmatrix   = (const float*)d_in[10];
    float* out = (float*)d_out;

    int N = in_sizes[0] / 17;            // lighting [N,17]
    int blocks = NPROD + 16 * N;

    k_fused<<<blocks, 256>>>(skinColor, lighting, illA, illF, pcaMeans,
                             pcaComp, tmatrix, mel, blood, shade, spec,
                             out, N);
}

// round 9
// speedup vs baseline: 2.1050x; 1.0362x over previous
#include <cuda_runtime.h>
#include <cuda_fp16.h>
#include <math.h>

// ---------------------------------------------------------------------------
// Decoder pipeline (2 launches, un-fused after R7/R8 showed the spin-wait
// fusion stalls the chip):
//   k_prep : bid 0        -> per-image lighting precompute -> g_params, b out
//            bids 1..1024 -> transpose skinColor[33,256,256] ->
//                            g_tex16 [65536][32] fp16 (64B rows, 64 texels/blk)
//                            + g_texE4 quad plane (8B/texel)
//   k_main : warp-cooperative gather (8 lanes x 4 pixel-slots), paired x-loads,
//            half2 bilinear+dot, fused elementwise, all outputs
// Output layout (flat f32): rgb[N*3*S], shade[N*S], spec[N*3*S], blood[N*S],
//   mel[N*S], b[N*2], raw[N*3*S]   (S=4096)
// ---------------------------------------------------------------------------

#define NPIX    65536
#define IMG2    4096
#define MAXN    256
#define TROW    40          // smem transpose row pitch in halves (80B)

__device__ __half  g_tex16[(NPIX + 16) * 32];   // 4 MB, 64B per texel row (+pad)
__device__ uint2   g_texE4[NPIX + 16];          // 512 KB quad plane
__device__ float   g_params[MAXN * 128];        // ES[108] G2[9] lc[3]

__constant__ float c_S0[33] = {94.8f,104.8f,105.9f,96.8f,113.9f,125.6f,125.5f,121.3f,121.3f,113.5f,113.1f,110.8f,106.5f,108.8f,105.3f,104.4f,100.0f,96.0f,95.1f,89.1f,90.5f,90.3f,88.4f,84.0f,85.1f,81.9f,82.6f,84.9f,81.3f,71.9f,74.3f,76.4f,63.3f};
__constant__ float c_S1[33] = {43.4f,46.3f,43.9f,37.1f,36.7f,35.9f,32.6f,27.9f,24.3f,20.1f,16.2f,13.2f,8.6f,6.1f,4.2f,1.9f,0.0f,-1.6f,-3.5f,-3.5f,-5.8f,-7.2f,-8.6f,-9.5f,-10.9f,-10.7f,-12.0f,-14.0f,-13.6f,-12.0f,-13.3f,-12.9f,-10.6f};
__constant__ float c_S2[33] = {-1.1f,-0.5f,-0.7f,-1.2f,-2.6f,-2.9f,-2.8f,-2.6f,-2.6f,-1.8f,-1.5f,-1.3f,-1.2f,-1.0f,-0.5f,-0.3f,0.0f,0.2f,0.5f,2.1f,3.2f,4.1f,4.7f,5.1f,6.7f,7.3f,8.6f,9.8f,10.2f,8.3f,9.6f,8.5f,7.0f};
__constant__ float c_X[9]  = {3.2406f,-1.537f,-0.498f,-0.968f,1.8758f,0.0415f,0.0557f,-0.204f,1.057f};

__device__ __forceinline__ void precompute_image(
    int n, const float* lp, const float* illA, const float* illF,
    const float* pcaMeans, const float* pcaComp, const float* tmat,
    float* outB)
{
    float mx = lp[0];
#pragma unroll
    for (int j = 1; j < 14; j++) mx = fmaxf(mx, lp[j]);
    float w[14], wsum = 0.f;
#pragma unroll
    for (int j = 0; j < 14; j++) { w[j] = expf(lp[j] - mx); wsum += w[j]; }
    float winv = 1.f / wsum;
    float wA = w[0] * winv, wD = w[1] * winv;
    float fw[12];
#pragma unroll
    for (int j = 0; j < 12; j++) fw[j] = w[j + 2] * winv;

    float colorTemp = 1.f / (1.f + expf(-lp[14]));
    float b0 = 6.f / (1.f + expf(-lp[15])) - 3.f;
    float b1 = 6.f / (1.f + expf(-lp[16])) - 3.f;
    outB[2 * n] = b0; outB[2 * n + 1] = b1;

    float t = colorTemp * 21000.f + 4000.f;
    float it = 1.f / t;
    float x = (t <= 7000.f)
        ? ((-4607000000.f * it + 2967800.f) * it + 99.11f) * it + 0.244063f
        : ((-2006400000.f * it + 1901800.f) * it + 247.48f) * it + 0.23704f;
    float y  = -3.f * x * x + 2.87f * x - 0.275f;
    float m  = 0.0241f + 0.2562f * x - 0.7341f * y;
    float m1 = (-1.3515f - 1.7703f * x + 5.9114f * y) / m;
    float m2 = (0.03f - 31.4424f * x + 30.0717f * y) / m;
    float s[33]; float ssum = 0.f;
#pragma unroll
    for (int k = 0; k < 33; k++) { s[k] = c_S0[k] + m1 * c_S1[k] + m2 * c_S2[k]; ssum += s[k]; }
    float sinv = 1.f / ssum;

    float e[33]; float esum = 0.f;
    for (int k = 0; k < 33; k++) {
        float ef = 0.f;
#pragma unroll
        for (int j = 0; j < 12; j++) ef += fw[j] * illF[k * 12 + j];
        float ev = wA * illA[k] + wD * s[k] * sinv + ef;
        e[k] = ev; esum += ev;
    }
    float einv = 1.f / esum;

    float lc[3] = {0.f, 0.f, 0.f};
    float* P = g_params + (size_t)n * 128;
    for (int c = 0; c < 3; c++) {
        for (int k = 0; k < 33; k++) {
            int i = c * 33 + k;
            float Sv = fmaxf(b0 * pcaComp[2 * i] + b1 * pcaComp[2 * i + 1] + pcaMeans[i], 0.f);
            lc[c] += Sv;
            P[c * 36 + k] = e[k] * einv * Sv;
        }
        P[c * 36 + 33] = 0.f; P[c * 36 + 34] = 0.f; P[c * 36 + 35] = 0.f;
    }

    float tx = (b0 * (1.f / 3.f) + 1.f) * 0.5f * 127.f;
    float ty = (b1 * (1.f / 3.f) + 1.f) * 0.5f * 127.f;
    float fx0 = floorf(tx), fy0 = floorf(ty);
    float wx = tx - fx0, wy = ty - fy0;
    int x0 = min(max((int)fx0, 0), 127), y0 = min(max((int)fy0, 0), 127);
    int x1 = min(x0 + 1, 127),           y1 = min(y0 + 1, 127);
    float w00 = (1.f - wx) * (1.f - wy), w01 = wx * (1.f - wy);
    float w10 = (1.f - wx) * wy,         w11 = wx * wy;
    float T[9];
#pragma unroll
    for (int ch = 0; ch < 9; ch++) {
        const float* tp = tmat + (size_t)ch * 128 * 128;
        T[ch] = w00 * tp[y0 * 128 + x0] + w01 * tp[y0 * 128 + x1]
              + w10 * tp[y1 * 128 + x0] + w11 * tp[y1 * 128 + x1];
    }
    for (int o = 0; o < 3; o++)
        for (int c = 0; c < 3; c++) {
            float g = c_X[o * 3 + 0] * T[c * 3 + 0]
                    + c_X[o * 3 + 1] * T[c * 3 + 1]
                    + c_X[o * 3 + 2] * T[c * 3 + 2];
            P[108 + o * 3 + c] = g / lc[c];
        }
    P[117] = lc[0]; P[118] = lc[1]; P[119] = lc[2];
}

// --- prep: precompute (bid 0) + transpose (bids 1..1024) ---------------------
__global__ void __launch_bounds__(256) k_prep(
    const float* __restrict__ sc,
    const float* __restrict__ lighting, const float* __restrict__ illA,
    const float* __restrict__ illF, const float* __restrict__ pcaMeans,
    const float* __restrict__ pcaComp, const float* __restrict__ tmat,
    float* __restrict__ outB, int N)
{
    const int bid = blockIdx.x;
    const int tid = threadIdx.x;

    if (bid == 0) {
        if (tid < N)
            precompute_image(tid, lighting + (size_t)tid * 17, illA, illF,
                             pcaMeans, pcaComp, tmat, outB);
        return;
    }

    __shared__ __align__(16) __half tile[64 * TROW];   // 5 KB
    const int base = (bid - 1) * 64;     // 64 texels per block
    const int texl = tid & 63;           // local texel 0..63
    const int part = tid >> 6;           // channel octet 0..3
    const int p    = base + texl;

    // 8 coalesced channel reads per thread (MLP=8)
    float v[8];
#pragma unroll
    for (int c = 0; c < 8; c++) v[c] = sc[(size_t)(part * 8 + c) * NPIX + p];
#pragma unroll
    for (int c = 0; c < 8; c++)
        tile[texl * TROW + part * 8 + c] = __float2half_rn(v[c]);

    // E-plane quad (octet group 0 handles it)
    if (part == 0) {
        const float* sc32 = sc + (size_t)32 * NPIX;
        const int pn  = min(p + 1,   NPIX - 1);
        const int pd  = min(p + 256, NPIX - 1);
        const int pdn = min(p + 257, NPIX - 1);
        __half2 top = __floats2half2_rn(sc32[p],  sc32[pn]);
        __half2 bot = __floats2half2_rn(sc32[pd], sc32[pdn]);
        uint2 u;
        u.x = *reinterpret_cast<unsigned*>(&top);
        u.y = *reinterpret_cast<unsigned*>(&bot);
        g_texE4[p] = u;
    }
    __syncthreads();

    // contiguous 4 KB row write: 256 uint4, one per thread
    uint4* dst = reinterpret_cast<uint4*>(g_tex16) + (size_t)base * 4;
    const int texw = tid >> 2, pw = tid & 3;
    dst[(size_t)texw * 4 + pw] =
        reinterpret_cast<const uint4*>(tile + texw * TROW)[pw];
}

// --- main kernel -------------------------------------------------------------
// Warp = 4 pixel-slots x 8 lanes. Lane owns 1 pixel (phase A/C). Phase B:
// 8 rounds; round r gathers pixel {slot*8+r}: lane sub covers x-side (sub>>2)
// and channel octet (sub&3) via one 16B load per y-row (x-pair rows contiguous
// 128B). Bilinear + ES dots in half2; (t0,t1) butterfly packed in half2.
__global__ void __launch_bounds__(256, 4) k_main(
    const float* __restrict__ mel, const float* __restrict__ blood,
    const float* __restrict__ shade, const float* __restrict__ spec,
    float* __restrict__ out, int N)
{
    const int n    = blockIdx.y;
    const int tid  = threadIdx.x;
    const int lane = tid & 31;
    const int sub  = lane & 7;

    __shared__ float sp[120];
    if (tid < 120) sp[tid] = g_params[(size_t)n * 128 + tid];
    __syncthreads();

    const size_t NS = (size_t)N * IMG2;
    float* o_rgb   = out;
    float* o_shade = out + 3 * NS;
    float* o_spec  = out + 4 * NS;
    float* o_blood = out + 7 * NS;
    float* o_mel   = out + 8 * NS;
    float* o_raw   = out + 9 * NS + 2 * (size_t)N;

    // ----- Phase A -----
    const int p   = blockIdx.x * 256 + tid;
    const size_t idx = (size_t)n * IMG2 + p;
    const float mv = mel[idx], bv = blood[idx], sv = shade[idx];
    const float sv0 = spec[((size_t)n * 3 + 0) * IMG2 + p];
    const float sv1 = spec[((size_t)n * 3 + 1) * IMG2 + p];
    const float sv2 = spec[((size_t)n * 3 + 2) * IMG2 + p];

    const float ms = 2.f / (1.f + __expf(-mv)) - 1.f;
    const float bs = 2.f / (1.f + __expf(-bv)) - 1.f;

    const float tx = (ms + 1.f) * 127.5f;
    const float ty = (bs + 1.f) * 127.5f;
    const float fx0 = floorf(tx), fy0 = floorf(ty);
    float wx = tx - fx0, wy = ty - fy0;
    const int x0 = min(max((int)fx0, 0), 255);
    const int y0 = min(max((int)fy0, 0), 255);
    const int y1 = min(y0 + 1, 255);
    const int off00 = y0 * 256 + x0;     // < 65536
    const int off10 = y1 * 256 + x0;     // < 65536

    const float w00 = (1.f - wx) * (1.f - wy), w01 = wx * (1.f - wy);
    const float w10 = (1.f - wx) * wy,         w11 = wx * wy;

    const float shadeE = __expf(sv);
    const float se0 = __expf(sv0) * sp[117];
    const float se1 = __expf(sv1) * sp[118];
    const float se2 = __expf(sv2) * sp[119];

    // channel-32: one 8B quad load per pixel
    float er;
    {
        uint2 u = g_texE4[off00];
        __half2 th = *reinterpret_cast<__half2*>(&u.x);
        __half2 bh = *reinterpret_cast<__half2*>(&u.y);
        float2 tf = __half22float2(th);
        float2 bf = __half22float2(bh);
        er = w00 * tf.x + w01 * tf.y + w10 * bf.x + w11 * bf.y;
    }
    float d0 = sp[32]  * er;
    float d1 = sp[68]  * er;
    float d2 = sp[104] * er;

    o_mel[idx]   = ms;
    o_blood[idx] = bs;
    o_shade[idx] = shadeE;
    {
        const size_t b3 = ((size_t)n * 3) * IMG2 + p;
        o_spec[b3] = se0; o_spec[b3 + IMG2] = se1; o_spec[b3 + 2 * IMG2] = se2;
    }

    const unsigned packedOff = (unsigned)off00 | ((unsigned)off10 << 16);
    unsigned wbits;
    {
        __half2 wpack = __floats2half2_rn(wx, wy);
        wbits = *reinterpret_cast<unsigned*>(&wpack);
    }

    // ----- Phase B: cooperative gather -----
    const int k0 = (sub & 3) * 8;
    __half2 esA[4], esB[4], esC[4];
#pragma unroll
    for (int j = 0; j < 4; j++) {
        esA[j] = __floats2half2_rn(sp[      k0 + 2*j], sp[      k0 + 2*j + 1]);
        esB[j] = __floats2half2_rn(sp[36  + k0 + 2*j], sp[36  + k0 + 2*j + 1]);
        esC[j] = __floats2half2_rn(sp[72  + k0 + 2*j], sp[72  + k0 + 2*j + 1]);
    }

    const uint4* texu = reinterpret_cast<const uint4*>(g_tex16);

#pragma unroll
    for (int r = 0; r < 8; r++) {
        const int src = (lane & 24) + r;
        const unsigned po = __shfl_sync(0xffffffffu, packedOff, src);
        const unsigned pw = __shfl_sync(0xffffffffu, wbits, src);
        const int o00 = (int)(po & 0xffffu);
        const int o10 = (int)(po >> 16);
        float swx, swy;
        {
            __half2 wh = *reinterpret_cast<const __half2*>(&pw);
            float2 wf = __half22float2(wh);
            swx = wf.x; swy = wf.y;
        }
        const float wxs = (sub < 4) ? (1.f - swx) : swx;
        const __half2 ay2 = __float2half2_rn(wxs * (1.f - swy));
        const __half2 by2 = __float2half2_rn(wxs * swy);

        const uint4 vy0 = texu[(size_t)o00 * 4 + sub];
        const uint4 vy1 = texu[(size_t)o10 * 4 + sub];
        const __half2* a = reinterpret_cast<const __half2*>(&vy0);
        const __half2* b = reinterpret_cast<const __half2*>(&vy1);

        __half2 r0 = __hfma2(by2, b[0], __hmul2(ay2, a[0]));
        __half2 r1 = __hfma2(by2, b[1], __hmul2(ay2, a[1]));
        __half2 r2 = __hfma2(by2, b[2], __hmul2(ay2, a[2]));
        __half2 r3 = __hfma2(by2, b[3], __hmul2(ay2, a[3]));

        __half2 acc0 = __hmul2(esA[0], r0);
        acc0 = __hfma2(esA[1], r1, acc0);
        acc0 = __hfma2(esA[2], r2, acc0);
        acc0 = __hfma2(esA[3], r3, acc0);
        __half2 acc1 = __hmul2(esB[0], r0);
        acc1 = __hfma2(esB[1], r1, acc1);
        acc1 = __hfma2(esB[2], r2, acc1);
        acc1 = __hfma2(esB[3], r3, acc1);
        __half2 acc2 = __hmul2(esC[0], r0);
        acc2 = __hfma2(esC[1], r1, acc2);
        acc2 = __hfma2(esC[2], r2, acc2);
        acc2 = __hfma2(esC[3], r3, acc2);

        __half2 t01 = __halves2half2(
            __hadd(__low2half(acc0), __high2half(acc0)),
            __hadd(__low2half(acc1), __high2half(acc1)));
        float t2 = __low2float(acc2) + __high2float(acc2);

        unsigned u01 = *reinterpret_cast<unsigned*>(&t01);
        {
            unsigned o = __shfl_xor_sync(0xffffffffu, u01, 4);
            __half2 hv = __hadd2(*reinterpret_cast<__half2*>(&u01),
                                 *reinterpret_cast<__half2*>(&o));
            u01 = *reinterpret_cast<unsigned*>(&hv);
        }
        t2 += __shfl_xor_sync(0xffffffffu, t2, 4);
        {
            unsigned o = __shfl_xor_sync(0xffffffffu, u01, 2);
            __half2 hv = __hadd2(*reinterpret_cast<__half2*>(&u01),
                                 *reinterpret_cast<__half2*>(&o));
            u01 = *reinterpret_cast<unsigned*>(&hv);
        }
        t2 += __shfl_xor_sync(0xffffffffu, t2, 2);
        {
            unsigned o = __shfl_xor_sync(0xffffffffu, u01, 1);
            __half2 hv = __hadd2(*reinterpret_cast<__half2*>(&u01),
                                 *reinterpret_cast<__half2*>(&o));
            u01 = *reinterpret_cast<unsigned*>(&hv);
        }
        t2 += __shfl_xor_sync(0xffffffffu, t2, 1);

        if (sub == r) {
            __half2 hv = *reinterpret_cast<__half2*>(&u01);
            d0 += __low2float(hv);
            d1 += __high2float(hv);
            d2 += t2;
        }
    }

    // ----- Phase C -----
    const float raw0 = shadeE * d0 + se0;
    const float raw1 = shadeE * d1 + se1;
    const float raw2 = shadeE * d2 + se2;
    const float rr = fmaxf(sp[108] * raw0 + sp[109] * raw1 + sp[110] * raw2, 0.f);
    const float rg = fmaxf(sp[111] * raw0 + sp[112] * raw1 + sp[113] * raw2, 0.f);
    const float rb = fmaxf(sp[114] * raw0 + sp[115] * raw1 + sp[116] * raw2, 0.f);

    const size_t b3 = ((size_t)n * 3) * IMG2 + p;
    o_rgb[b3] = rr; o_rgb[b3 + IMG2] = rg; o_rgb[b3 + 2 * IMG2] = rb;
    o_raw[b3] = raw0; o_raw[b3 + IMG2] = raw1; o_raw[b3 + 2 * IMG2] = raw2;
}

// ---------------------------------------------------------------------------
extern "C" void kernel_launch(void* const* d_in, const int* in_sizes, int n_in,
                              void* d_out, int out_size) {
    const float* lighting  = (const float*)d_in[0];
    const float* mel       = (const float*)d_in[1];
    const float* blood     = (const float*)d_in[2];
    const float* shade     = (const float*)d_in[3];
    const float* spec      = (const float*)d_in[4];
    const float* illA      = (const float*)d_in[5];
    const float* illF      = (const float*)d_in[6];
    const float* pcaMeans  = (const float*)d_in[7];
    const float* pcaComp   = (const float*)d_in[8];
    const float* skinColor = (const float*)d_in[9];
    const float* tmatrix   = (const float*)d_in[10];
    float* out = (float*)d_out;

    int N = in_sizes[0] / 17;            // lighting [N,17]
    size_t NS = (size_t)N * IMG2;
    float* outB = out + 9 * NS;

    k_prep<<<1025, 256>>>(skinColor, lighting, illA, illF, pcaMeans,
                          pcaComp, tmatrix, outB, N);
    k_main<<<dim3(16, N), 256>>>(mel, blood, shade, spec, out, N);
}